// round 1
// baseline (speedup 1.0000x reference)
#include <cuda_runtime.h>

#define BB   2
#define TT   2048
#define DD   1024
#define HH   16
#define DHH  64
#define NROWS (BB * TT)   // 4096

// Scratch (allocation-free rule: __device__ globals)
__device__ float g_Q[NROWS * DD];
__device__ float g_K[NROWS * DD];
__device__ float g_V[NROWS * DD];
__device__ float g_A[NROWS * DD];

// C[n,m] = sum_k A[n,k] * Bw[m,k]   (A: NROWSxDD row-major, Bw: DDxDD row-major)
// 64x64 block tile, 256 threads, 4x4 per thread, K-tile 32.
__global__ void __launch_bounds__(256) gemm_nt(const float* __restrict__ A,
                                               const float* __restrict__ Bw,
                                               float* __restrict__ C) {
    __shared__ float As[32][65];
    __shared__ float Bs[32][65];
    const int tid = threadIdx.x;
    const int tx = tid & 15;
    const int ty = tid >> 4;
    const int n0 = blockIdx.y * 64;
    const int m0 = blockIdx.x * 64;

    float acc[4][4];
    #pragma unroll
    for (int i = 0; i < 4; i++)
        #pragma unroll
        for (int j = 0; j < 4; j++) acc[i][j] = 0.0f;

    for (int k0 = 0; k0 < DD; k0 += 32) {
        #pragma unroll
        for (int i = 0; i < 8; i++) {
            int lin = tid + i * 256;
            int r  = lin >> 5;   // 0..63
            int kk = lin & 31;   // 0..31
            As[kk][r] = A[(size_t)(n0 + r) * DD + k0 + kk];
            Bs[kk][r] = Bw[(size_t)(m0 + r) * DD + k0 + kk];
        }
        __syncthreads();
        #pragma unroll
        for (int kk = 0; kk < 32; kk++) {
            float a[4], b[4];
            #pragma unroll
            for (int i = 0; i < 4; i++) a[i] = As[kk][ty * 4 + i];
            #pragma unroll
            for (int j = 0; j < 4; j++) b[j] = Bs[kk][tx * 4 + j];
            #pragma unroll
            for (int i = 0; i < 4; i++)
                #pragma unroll
                for (int j = 0; j < 4; j++)
                    acc[i][j] = fmaf(a[i], b[j], acc[i][j]);
        }
        __syncthreads();
    }
    #pragma unroll
    for (int i = 0; i < 4; i++)
        #pragma unroll
        for (int j = 0; j < 4; j++)
            C[(size_t)(n0 + ty * 4 + i) * DD + m0 + tx * 4 + j] = acc[i][j];
}

// Sliding-window causal attention on (B,T,H*dh)-layout Q/K/V.
// Block: 64 threads = 64 queries of one (qtile, head, batch). Window: j in [i-128, i].
__global__ void __launch_bounds__(64) attn_kernel(const float* __restrict__ Q,
                                                  const float* __restrict__ K,
                                                  const float* __restrict__ V,
                                                  float* __restrict__ O) {
    // Qs element (query i, dim d) stored at d*64 + ((i + d) & 63): conflict-free
    // on both the store (threads vary d) and the compute read (threads vary i).
    __shared__ float Qs[64 * 64];
    __shared__ float Ks[64][64];   // [key][dim], broadcast reads
    __shared__ float Vs[64][64];

    const int t  = threadIdx.x;        // query index within tile / dim index when loading
    const int q0 = blockIdx.x * 64;
    const int h  = blockIdx.y;
    const int b  = blockIdx.z;
    const size_t rowbase = (size_t)b * TT;
    const int col0 = h * DHH;

    // Load Q tile (coalesced: thread = dim)
    #pragma unroll 4
    for (int i = 0; i < 64; i++)
        Qs[t * 64 + ((i + t) & 63)] = Q[(rowbase + q0 + i) * DD + col0 + t];

    const int i_global = q0 + t;
    float m = -1e30f, l = 0.0f;
    float acc[DHH];
    #pragma unroll
    for (int d = 0; d < DHH; d++) acc[d] = 0.0f;

    const int c_lo = (q0 >= 128) ? ((q0 - 128) >> 6) : 0;
    const int c_hi = q0 >> 6;

    for (int c = c_lo; c <= c_hi; c++) {
        __syncthreads();
        #pragma unroll 4
        for (int i = 0; i < 64; i++) {
            Ks[i][t] = K[(rowbase + (size_t)c * 64 + i) * DD + col0 + t];
            Vs[i][t] = V[(rowbase + (size_t)c * 64 + i) * DD + col0 + t];
        }
        __syncthreads();

        for (int j = 0; j < 64; j++) {
            const int key = c * 64 + j;
            if (key > i_global || (i_global - key) > 128) continue;
            float s0 = 0.f, s1 = 0.f, s2 = 0.f, s3 = 0.f;
            #pragma unroll
            for (int d = 0; d < DHH; d += 4) {
                s0 = fmaf(Qs[(d + 0) * 64 + ((t + d + 0) & 63)], Ks[j][d + 0], s0);
                s1 = fmaf(Qs[(d + 1) * 64 + ((t + d + 1) & 63)], Ks[j][d + 1], s1);
                s2 = fmaf(Qs[(d + 2) * 64 + ((t + d + 2) & 63)], Ks[j][d + 2], s2);
                s3 = fmaf(Qs[(d + 3) * 64 + ((t + d + 3) & 63)], Ks[j][d + 3], s3);
            }
            float s = ((s0 + s1) + (s2 + s3)) * 0.125f;  // 1/sqrt(64)

            const float mnew = fmaxf(m, s);
            const float corr = __expf(m - mnew);
            const float p    = __expf(s - mnew);
            l = l * corr + p;
            #pragma unroll
            for (int d = 0; d < DHH; d++)
                acc[d] = fmaf(acc[d], corr, p * Vs[j][d]);
            m = mnew;
        }
    }

    const float inv = 1.0f / l;
    #pragma unroll
    for (int d = 0; d < DHH; d++)
        O[(rowbase + i_global) * DD + col0 + d] = acc[d] * inv;
}

extern "C" void kernel_launch(void* const* d_in, const int* in_sizes, int n_in,
                              void* d_out, int out_size) {
    const float* x  = (const float*)d_in[0];
    const float* Wq = (const float*)d_in[1];
    const float* Wk = (const float*)d_in[2];
    const float* Wv = (const float*)d_in[3];
    const float* Wo = (const float*)d_in[4];
    float* out = (float*)d_out;

    float *Q, *K, *V, *A;
    cudaGetSymbolAddress((void**)&Q, g_Q);
    cudaGetSymbolAddress((void**)&K, g_K);
    cudaGetSymbolAddress((void**)&V, g_V);
    cudaGetSymbolAddress((void**)&A, g_A);

    dim3 ggrid(DD / 64, NROWS / 64);   // (16, 64)
    gemm_nt<<<ggrid, 256>>>(x, Wq, Q);
    gemm_nt<<<ggrid, 256>>>(x, Wk, K);
    gemm_nt<<<ggrid, 256>>>(x, Wv, V);

    attn_kernel<<<dim3(TT / 64, HH, BB), 64>>>(Q, K, V, A);

    gemm_nt<<<ggrid, 256>>>(A, Wo, out);
}

// round 2
// speedup vs baseline: 1.3523x; 1.3523x over previous
#include <cuda_runtime.h>

#define BB   2
#define TT   2048
#define DD   1024
#define HH   16
#define DHH  64
#define NROWS (BB * TT)   // 4096

// Scratch (allocation-free rule: __device__ globals)
__device__ float g_Q[NROWS * DD];
__device__ float g_K[NROWS * DD];
__device__ float g_V[NROWS * DD];
__device__ float g_A[NROWS * DD];

// ---------------------------------------------------------------------------
// C[n,m] = sum_k A[n,k] * Bw[m,k]   (A: NROWSxDD row-major, Bw: DDxDD row-major)
// 128x128 block tile, 256 threads, 8x8 per thread, BK=16, double-buffered.
// ---------------------------------------------------------------------------
#define BM 128
#define BN 128
#define BK 16
#define SPAD 4      // row stride BM+SPAD = 132 floats (528B, 16B-aligned)

__global__ void __launch_bounds__(256) gemm_nt(const float* __restrict__ A,
                                               const float* __restrict__ Bw,
                                               float* __restrict__ C) {
    __shared__ __align__(16) float As[2][BK][BM + SPAD];
    __shared__ __align__(16) float Bs[2][BK][BN + SPAD];

    const int tid = threadIdx.x;
    const int tx = tid & 15;          // 0..15
    const int ty = tid >> 4;          // 0..15
    const int n0 = blockIdx.y * BM;
    const int m0 = blockIdx.x * BN;

    // global-load mapping: thread loads one row's half k-tile (2 float4)
    const int lrow = tid >> 1;        // 0..127
    const int lk   = (tid & 1) * 8;   // 0 or 8

    const float* Aptr = A  + (size_t)(n0 + lrow) * DD + lk;
    const float* Bptr = Bw + (size_t)(m0 + lrow) * DD + lk;

    float4 pa0, pa1, pb0, pb1;

    // prologue: load k-tile 0 into buffer 0
    pa0 = *(const float4*)(Aptr + 0);
    pa1 = *(const float4*)(Aptr + 4);
    pb0 = *(const float4*)(Bptr + 0);
    pb1 = *(const float4*)(Bptr + 4);
    As[0][lk + 0][lrow] = pa0.x; As[0][lk + 1][lrow] = pa0.y;
    As[0][lk + 2][lrow] = pa0.z; As[0][lk + 3][lrow] = pa0.w;
    As[0][lk + 4][lrow] = pa1.x; As[0][lk + 5][lrow] = pa1.y;
    As[0][lk + 6][lrow] = pa1.z; As[0][lk + 7][lrow] = pa1.w;
    Bs[0][lk + 0][lrow] = pb0.x; Bs[0][lk + 1][lrow] = pb0.y;
    Bs[0][lk + 2][lrow] = pb0.z; Bs[0][lk + 3][lrow] = pb0.w;
    Bs[0][lk + 4][lrow] = pb1.x; Bs[0][lk + 5][lrow] = pb1.y;
    Bs[0][lk + 6][lrow] = pb1.z; Bs[0][lk + 7][lrow] = pb1.w;
    __syncthreads();

    float acc[8][8];
    #pragma unroll
    for (int i = 0; i < 8; i++)
        #pragma unroll
        for (int j = 0; j < 8; j++) acc[i][j] = 0.0f;

    const int KT = DD / BK;   // 64
    int cur = 0;

    for (int kt = 0; kt < KT; kt++) {
        if (kt + 1 < KT) {
            const float* ap = Aptr + (size_t)(kt + 1) * BK;
            const float* bp = Bptr + (size_t)(kt + 1) * BK;
            pa0 = *(const float4*)(ap + 0);
            pa1 = *(const float4*)(ap + 4);
            pb0 = *(const float4*)(bp + 0);
            pb1 = *(const float4*)(bp + 4);
        }

        #pragma unroll
        for (int k = 0; k < BK; k++) {
            float4 a0 = *(const float4*)&As[cur][k][ty * 8];
            float4 a1 = *(const float4*)&As[cur][k][ty * 8 + 4];
            float4 b0 = *(const float4*)&Bs[cur][k][tx * 8];
            float4 b1 = *(const float4*)&Bs[cur][k][tx * 8 + 4];
            float av[8] = {a0.x, a0.y, a0.z, a0.w, a1.x, a1.y, a1.z, a1.w};
            float bv[8] = {b0.x, b0.y, b0.z, b0.w, b1.x, b1.y, b1.z, b1.w};
            #pragma unroll
            for (int i = 0; i < 8; i++)
                #pragma unroll
                for (int j = 0; j < 8; j++)
                    acc[i][j] = fmaf(av[i], bv[j], acc[i][j]);
        }

        if (kt + 1 < KT) {
            const int nb = cur ^ 1;
            As[nb][lk + 0][lrow] = pa0.x; As[nb][lk + 1][lrow] = pa0.y;
            As[nb][lk + 2][lrow] = pa0.z; As[nb][lk + 3][lrow] = pa0.w;
            As[nb][lk + 4][lrow] = pa1.x; As[nb][lk + 5][lrow] = pa1.y;
            As[nb][lk + 6][lrow] = pa1.z; As[nb][lk + 7][lrow] = pa1.w;
            Bs[nb][lk + 0][lrow] = pb0.x; Bs[nb][lk + 1][lrow] = pb0.y;
            Bs[nb][lk + 2][lrow] = pb0.z; Bs[nb][lk + 3][lrow] = pb0.w;
            Bs[nb][lk + 4][lrow] = pb1.x; Bs[nb][lk + 5][lrow] = pb1.y;
            Bs[nb][lk + 6][lrow] = pb1.z; Bs[nb][lk + 7][lrow] = pb1.w;
            __syncthreads();
            cur = nb;
        }
    }

    // epilogue: write 8x8 tile (two float4 per row)
    #pragma unroll
    for (int i = 0; i < 8; i++) {
        float* crow = C + (size_t)(n0 + ty * 8 + i) * DD + m0 + tx * 8;
        float4 c0 = {acc[i][0], acc[i][1], acc[i][2], acc[i][3]};
        float4 c1 = {acc[i][4], acc[i][5], acc[i][6], acc[i][7]};
        *(float4*)(crow + 0) = c0;
        *(float4*)(crow + 4) = c1;
    }
}

// ---------------------------------------------------------------------------
// Sliding-window causal attention. Window: key in [i-128, i].
// Block: 128 threads = 64 queries x 2 dim-halves. Q in registers, acc[32]/thread.
// ---------------------------------------------------------------------------
__global__ void __launch_bounds__(128) attn_kernel(const float* __restrict__ Q,
                                                   const float* __restrict__ K,
                                                   const float* __restrict__ V,
                                                   float* __restrict__ O) {
    __shared__ __align__(16) float Ks[64][68];   // [key][dim], 68-pad
    __shared__ __align__(16) float Vs[64][68];

    const int tid  = threadIdx.x;
    const int q    = tid >> 1;        // query within tile 0..63
    const int half = tid & 1;         // which 32-dim half
    const int doff = half * 32;
    const int q0 = blockIdx.x * 64;
    const int h  = blockIdx.y;
    const int b  = blockIdx.z;
    const size_t rowbase = (size_t)b * TT;
    const int col0 = h * DHH;

    // Q for this (query, half) -> registers
    float qreg[32];
    {
        const float4* qp = (const float4*)(Q + (rowbase + q0 + q) * DD + col0 + doff);
        #pragma unroll
        for (int i = 0; i < 8; i++) {
            float4 v = qp[i];
            qreg[4 * i + 0] = v.x; qreg[4 * i + 1] = v.y;
            qreg[4 * i + 2] = v.z; qreg[4 * i + 3] = v.w;
        }
    }

    const int i_global = q0 + q;
    const int warp_q0  = q0 + ((tid >> 5) << 4);   // first query of this warp

    float m = -1e30f, l = 0.0f;
    float acc[32];
    #pragma unroll
    for (int d = 0; d < 32; d++) acc[d] = 0.0f;

    const int c_lo = (q0 >= 128) ? ((q0 - 128) >> 6) : 0;
    const int c_hi = q0 >> 6;

    for (int c = c_lo; c <= c_hi; c++) {
        const int kbase = c * 64;
        __syncthreads();
        {
            const float4* kp = (const float4*)(K + (rowbase + kbase + q) * DD + col0 + doff);
            const float4* vp = (const float4*)(V + (rowbase + kbase + q) * DD + col0 + doff);
            #pragma unroll
            for (int i = 0; i < 8; i++) {
                *(float4*)&Ks[q][doff + 4 * i] = kp[i];
                *(float4*)&Vs[q][doff + 4 * i] = vp[i];
            }
        }
        __syncthreads();

        // warp-uniform j bounds (queries in warp: warp_q0 .. warp_q0+15)
        int jlo = warp_q0 - 128 - kbase; if (jlo < 0) jlo = 0;
        int jhi = warp_q0 + 15 - kbase;  if (jhi > 63) jhi = 63;

        #pragma unroll 1
        for (int j = jlo; j <= jhi; j++) {
            const int key = kbase + j;
            const bool valid = (key <= i_global) && (key + 128 >= i_global);

            float s = 0.0f;
            #pragma unroll
            for (int i = 0; i < 8; i++) {
                float4 kv = *(const float4*)&Ks[j][doff + 4 * i];
                s = fmaf(qreg[4 * i + 0], kv.x, s);
                s = fmaf(qreg[4 * i + 1], kv.y, s);
                s = fmaf(qreg[4 * i + 2], kv.z, s);
                s = fmaf(qreg[4 * i + 3], kv.w, s);
            }
            s += __shfl_xor_sync(0xffffffffu, s, 1);
            s *= 0.125f;   // 1/sqrt(64)

            const float mnew = valid ? fmaxf(m, s) : m;
            const float corr = __expf(m - mnew);
            const float p    = valid ? __expf(s - mnew) : 0.0f;
            l = l * corr + p;
            #pragma unroll
            for (int i = 0; i < 8; i++) {
                float4 vv = *(const float4*)&Vs[j][doff + 4 * i];
                acc[4 * i + 0] = fmaf(acc[4 * i + 0], corr, p * vv.x);
                acc[4 * i + 1] = fmaf(acc[4 * i + 1], corr, p * vv.y);
                acc[4 * i + 2] = fmaf(acc[4 * i + 2], corr, p * vv.z);
                acc[4 * i + 3] = fmaf(acc[4 * i + 3], corr, p * vv.w);
            }
            m = mnew;
        }
    }

    const float inv = 1.0f / l;
    float4* op = (float4*)(O + (rowbase + i_global) * DD + col0 + doff);
    #pragma unroll
    for (int i = 0; i < 8; i++) {
        float4 o;
        o.x = acc[4 * i + 0] * inv; o.y = acc[4 * i + 1] * inv;
        o.z = acc[4 * i + 2] * inv; o.w = acc[4 * i + 3] * inv;
        op[i] = o;
    }
}

extern "C" void kernel_launch(void* const* d_in, const int* in_sizes, int n_in,
                              void* d_out, int out_size) {
    const float* x  = (const float*)d_in[0];
    const float* Wq = (const float*)d_in[1];
    const float* Wk = (const float*)d_in[2];
    const float* Wv = (const float*)d_in[3];
    const float* Wo = (const float*)d_in[4];
    float* out = (float*)d_out;

    float *Q, *K, *V, *A;
    cudaGetSymbolAddress((void**)&Q, g_Q);
    cudaGetSymbolAddress((void**)&K, g_K);
    cudaGetSymbolAddress((void**)&V, g_V);
    cudaGetSymbolAddress((void**)&A, g_A);

    dim3 ggrid(DD / BN, NROWS / BM);   // (8, 32)
    gemm_nt<<<ggrid, 256>>>(x, Wq, Q);
    gemm_nt<<<ggrid, 256>>>(x, Wk, K);
    gemm_nt<<<ggrid, 256>>>(x, Wv, V);

    attn_kernel<<<dim3(TT / 64, HH, BB), 128>>>(Q, K, V, A);

    gemm_nt<<<ggrid, 256>>>(A, Wo, out);
}

// round 4
// speedup vs baseline: 2.4496x; 1.8114x over previous
#include <cuda_runtime.h>
#include <cuda_bf16.h>
#include <cstdint>

#define BB 2
#define TT 2048
#define DD 1024
#define HH 16
#define DHH 64
#define NROWS (BB*TT)   // 4096

// Scratch (allocation-free rule: __device__ globals)
__device__ float g_Q[NROWS*DD];
__device__ float g_K[NROWS*DD];
__device__ float g_V[NROWS*DD];
__device__ __nv_bfloat16 g_xh[NROWS*DD];
__device__ __nv_bfloat16 g_xl[NROWS*DD];
__device__ __nv_bfloat16 g_Ah[NROWS*DD];
__device__ __nv_bfloat16 g_Al[NROWS*DD];
__device__ __nv_bfloat16 g_Wh[4*DD*DD];
__device__ __nv_bfloat16 g_Wl[4*DD*DD];

// ---------------------------------------------------------------------------
// helpers (portable PTX only: cp.async / ldmatrix / mma.sync — no tcgen05)
// ---------------------------------------------------------------------------
__device__ __forceinline__ uint32_t smem_u32(const void* p) {
    uint32_t a;
    asm("{ .reg .u64 t; cvta.to.shared.u64 t, %1; cvt.u32.u64 %0, t; }" : "=r"(a) : "l"(p));
    return a;
}
__device__ __forceinline__ void cp16(uint32_t dst, const void* src) {
    asm volatile("cp.async.cg.shared.global [%0], [%1], 16;" :: "r"(dst), "l"(src));
}
#define CP_COMMIT() asm volatile("cp.async.commit_group;" ::: "memory")
#define CP_WAIT(n)  asm volatile("cp.async.wait_group %0;" :: "n"(n) : "memory")

__device__ __forceinline__ void ldm_x4(uint32_t* r, uint32_t addr) {
    asm volatile("ldmatrix.sync.aligned.m8n8.x4.shared.b16 {%0,%1,%2,%3}, [%4];"
                 : "=r"(r[0]), "=r"(r[1]), "=r"(r[2]), "=r"(r[3]) : "r"(addr));
}
__device__ __forceinline__ void mma_bf16(float* d, const uint32_t* a, uint32_t b0, uint32_t b1) {
    asm volatile(
        "mma.sync.aligned.m16n8k16.row.col.f32.bf16.bf16.f32 "
        "{%0,%1,%2,%3}, {%4,%5,%6,%7}, {%8,%9}, {%0,%1,%2,%3};"
        : "+f"(d[0]), "+f"(d[1]), "+f"(d[2]), "+f"(d[3])
        : "r"(a[0]), "r"(a[1]), "r"(a[2]), "r"(a[3]), "r"(b0), "r"(b1));
}

// ---------------------------------------------------------------------------
// split fp32 -> (bf16 hi, bf16 lo)
// ---------------------------------------------------------------------------
__global__ void __launch_bounds__(256) split_kernel(const float* __restrict__ in,
                                                    __nv_bfloat16* __restrict__ hi,
                                                    __nv_bfloat16* __restrict__ lo,
                                                    int n4) {
    int i = blockIdx.x * blockDim.x + threadIdx.x;
    if (i >= n4) return;
    float4 v = ((const float4*)in)[i];
    __align__(8) __nv_bfloat16 h[4], l[4];
    h[0] = __float2bfloat16(v.x); l[0] = __float2bfloat16(v.x - __bfloat162float(h[0]));
    h[1] = __float2bfloat16(v.y); l[1] = __float2bfloat16(v.y - __bfloat162float(h[1]));
    h[2] = __float2bfloat16(v.z); l[2] = __float2bfloat16(v.z - __bfloat162float(h[2]));
    h[3] = __float2bfloat16(v.w); l[3] = __float2bfloat16(v.w - __bfloat162float(h[3]));
    ((uint2*)hi)[i] = *(const uint2*)h;
    ((uint2*)lo)[i] = *(const uint2*)l;
}

// ---------------------------------------------------------------------------
// C[n,m] = sum_k A[n,k]*B[m,k] in bf16x3 via mma.sync.m16n8k16.
// CTA tile 128x128, BK=32, 3-stage cp.async pipeline, 8 warps (4m x 2n),
// warp tile 32x64. Smem row = 64B (32 bf16), chunk swizzle c ^= (row>>1)&3.
// Stage layout (32KB): Ah +0, Al +8192, Bh +16384, Bl +24576.
// ---------------------------------------------------------------------------
#define NSTAGE 3
#define STG 32768
#define GEMM_SMEM (NSTAGE * STG)

__global__ void __launch_bounds__(256, 1) gemm_bf16x3(
    const __nv_bfloat16* __restrict__ Ahg, const __nv_bfloat16* __restrict__ Alg,
    const __nv_bfloat16* __restrict__ Bhg, const __nv_bfloat16* __restrict__ Blg,
    float* __restrict__ C) {
    extern __shared__ __align__(128) char smem[];
    const uint32_t sbase = smem_u32(smem);
    const int tid  = threadIdx.x;
    const int wid  = tid >> 5;
    const int lane = tid & 31;
    const int n0 = blockIdx.y * 128;   // output-row block (rows of A)
    const int m0 = blockIdx.x * 128;   // output-col block (rows of B)

    const int warp_m = (wid & 3) * 32;   // warp row offset within tile
    const int warp_n = (wid >> 2) * 64;  // warp col offset within tile

    const int KT = DD / 32;   // 32 k-stages

    // ---- stage loader: 8 cp.async/thread ----
    const int lrow = tid >> 1;            // 0..127
    const int lc0  = (tid & 1) * 2;       // chunk 0/2
    auto load_stage = [&](int s) {
        const int k0 = s * 32;
        const uint32_t stg = sbase + (uint32_t)(s % NSTAGE) * STG;
        #pragma unroll
        for (int cc = 0; cc < 2; cc++) {
            const int c = lc0 + cc;
            const uint32_t d = (uint32_t)(lrow * 64 + ((c ^ ((lrow >> 1) & 3)) * 16));
            const size_t sa = (size_t)(n0 + lrow) * DD + k0 + c * 8;
            const size_t sb = (size_t)(m0 + lrow) * DD + k0 + c * 8;
            cp16(stg + 0     + d, Ahg + sa);
            cp16(stg + 8192  + d, Alg + sa);
            cp16(stg + 16384 + d, Bhg + sb);
            cp16(stg + 24576 + d, Blg + sb);
        }
        CP_COMMIT();
    };

    load_stage(0);
    load_stage(1);
    load_stage(2);

    float acc[2][8][4];
    #pragma unroll
    for (int mt = 0; mt < 2; mt++)
        #pragma unroll
        for (int nt = 0; nt < 8; nt++)
            #pragma unroll
            for (int i = 0; i < 4; i++) acc[mt][nt][i] = 0.0f;

    // ldmatrix lane-address components (fixed per thread)
    const int a_r    = (lane & 15);       // row within m16 tile
    const int a_csel = (lane >> 4);       // 0/1 -> k chunk
    const int b_g    = (lane >> 3);       // 0..3
    const int b_r    = ((b_g >> 1) << 3) + (lane & 7);  // row within n16 tile
    const int b_csel = (b_g & 1);

    for (int s = 0; s < KT; s++) {
        CP_WAIT(NSTAGE - 1);     // stage s resident (empty-commit keeps count)
        __syncthreads();

        const uint32_t stg = sbase + (uint32_t)(s % NSTAGE) * STG;
        #pragma unroll
        for (int kk = 0; kk < 32; kk += 16) {
            const int cbase = kk >> 3;
            uint32_t ah[2][4], al[2][4], bh[4][4], bl[4][4];
            #pragma unroll
            for (int mt = 0; mt < 2; mt++) {
                const int r = warp_m + mt * 16 + a_r;
                const int c = (cbase + a_csel) ^ ((r >> 1) & 3);
                const uint32_t ad = (uint32_t)(r * 64 + c * 16);
                ldm_x4(ah[mt], stg + 0    + ad);
                ldm_x4(al[mt], stg + 8192 + ad);
            }
            #pragma unroll
            for (int nt4 = 0; nt4 < 4; nt4++) {
                const int r = warp_n + nt4 * 16 + b_r;
                const int c = (cbase + b_csel) ^ ((r >> 1) & 3);
                const uint32_t bd = (uint32_t)(r * 64 + c * 16);
                ldm_x4(bh[nt4], stg + 16384 + bd);
                ldm_x4(bl[nt4], stg + 24576 + bd);
            }
            #pragma unroll
            for (int mt = 0; mt < 2; mt++)
                #pragma unroll
                for (int nt = 0; nt < 8; nt++) {
                    const uint32_t bh0 = bh[nt >> 1][(nt & 1) * 2];
                    const uint32_t bh1 = bh[nt >> 1][(nt & 1) * 2 + 1];
                    const uint32_t bl0 = bl[nt >> 1][(nt & 1) * 2];
                    const uint32_t bl1 = bl[nt >> 1][(nt & 1) * 2 + 1];
                    mma_bf16(acc[mt][nt], ah[mt], bh0, bh1);
                    mma_bf16(acc[mt][nt], al[mt], bh0, bh1);
                    mma_bf16(acc[mt][nt], ah[mt], bl0, bl1);
                }
        }
        __syncthreads();
        if (s + NSTAGE < KT) load_stage(s + NSTAGE);
        else                 CP_COMMIT();          // empty group keeps wait math valid
    }

    // epilogue: d-frag lane mapping (m16n8): rows lane/4 (+8), cols 2*(lane%4)(+1)
    #pragma unroll
    for (int mt = 0; mt < 2; mt++)
        #pragma unroll
        for (int nt = 0; nt < 8; nt++) {
            const int r   = n0 + warp_m + mt * 16 + (lane >> 2);
            const int col = m0 + warp_n + nt * 8 + (lane & 3) * 2;
            float2 v0 = {acc[mt][nt][0], acc[mt][nt][1]};
            float2 v1 = {acc[mt][nt][2], acc[mt][nt][3]};
            *(float2*)(C + (size_t)r * DD + col)       = v0;
            *(float2*)(C + (size_t)(r + 8) * DD + col) = v1;
        }
}

// ---------------------------------------------------------------------------
// Sliding-window causal attention (fp32 in, bf16 hi/lo out). Unchanged math.
// ---------------------------------------------------------------------------
__global__ void __launch_bounds__(128) attn_kernel(const float* __restrict__ Q,
                                                   const float* __restrict__ K,
                                                   const float* __restrict__ V,
                                                   __nv_bfloat16* __restrict__ Ah,
                                                   __nv_bfloat16* __restrict__ Al) {
    __shared__ __align__(16) float Ks[64][68];
    __shared__ __align__(16) float Vs[64][68];

    const int tid  = threadIdx.x;
    const int q    = tid >> 1;
    const int half = tid & 1;
    const int doff = half * 32;
    const int q0 = blockIdx.x * 64;
    const int h  = blockIdx.y;
    const int b  = blockIdx.z;
    const size_t rowbase = (size_t)b * TT;
    const int col0 = h * DHH;

    float qreg[32];
    {
        const float4* qp = (const float4*)(Q + (rowbase + q0 + q) * DD + col0 + doff);
        #pragma unroll
        for (int i = 0; i < 8; i++) {
            float4 v = qp[i];
            qreg[4 * i + 0] = v.x; qreg[4 * i + 1] = v.y;
            qreg[4 * i + 2] = v.z; qreg[4 * i + 3] = v.w;
        }
    }

    const int i_global = q0 + q;
    const int warp_q0  = q0 + ((tid >> 5) << 4);

    float m = -1e30f, l = 0.0f;
    float acc[32];
    #pragma unroll
    for (int d = 0; d < 32; d++) acc[d] = 0.0f;

    const int c_lo = (q0 >= 128) ? ((q0 - 128) >> 6) : 0;
    const int c_hi = q0 >> 6;

    for (int c = c_lo; c <= c_hi; c++) {
        const int kbase = c * 64;
        __syncthreads();
        {
            const float4* kp = (const float4*)(K + (rowbase + kbase + q) * DD + col0 + doff);
            const float4* vp = (const float4*)(V + (rowbase + kbase + q) * DD + col0 + doff);
            #pragma unroll
            for (int i = 0; i < 8; i++) {
                *(float4*)&Ks[q][doff + 4 * i] = kp[i];
                *(float4*)&Vs[q][doff + 4 * i] = vp[i];
            }
        }
        __syncthreads();

        int jlo = warp_q0 - 128 - kbase; if (jlo < 0) jlo = 0;
        int jhi = warp_q0 + 15 - kbase;  if (jhi > 63) jhi = 63;

        #pragma unroll 1
        for (int j = jlo; j <= jhi; j++) {
            const int key = kbase + j;
            const bool valid = (key <= i_global) && (key + 128 >= i_global);

            float s = 0.0f;
            #pragma unroll
            for (int i = 0; i < 8; i++) {
                float4 kv = *(const float4*)&Ks[j][doff + 4 * i];
                s = fmaf(qreg[4 * i + 0], kv.x, s);
                s = fmaf(qreg[4 * i + 1], kv.y, s);
                s = fmaf(qreg[4 * i + 2], kv.z, s);
                s = fmaf(qreg[4 * i + 3], kv.w, s);
            }
            s += __shfl_xor_sync(0xffffffffu, s, 1);
            s *= 0.125f;

            const float mnew = valid ? fmaxf(m, s) : m;
            const float corr = __expf(m - mnew);
            const float p    = valid ? __expf(s - mnew) : 0.0f;
            l = l * corr + p;
            #pragma unroll
            for (int i = 0; i < 8; i++) {
                float4 vv = *(const float4*)&Vs[j][doff + 4 * i];
                acc[4 * i + 0] = fmaf(acc[4 * i + 0], corr, p * vv.x);
                acc[4 * i + 1] = fmaf(acc[4 * i + 1], corr, p * vv.y);
                acc[4 * i + 2] = fmaf(acc[4 * i + 2], corr, p * vv.z);
                acc[4 * i + 3] = fmaf(acc[4 * i + 3], corr, p * vv.w);
            }
            m = mnew;
        }
    }

    const float inv = 1.0f / l;
    __align__(16) __nv_bfloat16 hb[32], lb[32];
    #pragma unroll
    for (int d = 0; d < 32; d++) {
        float v = acc[d] * inv;
        __nv_bfloat16 hh = __float2bfloat16(v);
        hb[d] = hh;
        lb[d] = __float2bfloat16(v - __bfloat162float(hh));
    }
    size_t o = (rowbase + i_global) * DD + col0 + doff;
    uint4* hp = (uint4*)(Ah + o);
    uint4* lp = (uint4*)(Al + o);
    const uint4* hs = (const uint4*)hb;
    const uint4* ls = (const uint4*)lb;
    #pragma unroll
    for (int i = 0; i < 4; i++) { hp[i] = hs[i]; lp[i] = ls[i]; }
}

// ---------------------------------------------------------------------------
extern "C" void kernel_launch(void* const* d_in, const int* in_sizes, int n_in,
                              void* d_out, int out_size) {
    const float* x  = (const float*)d_in[0];
    const float* Wq = (const float*)d_in[1];
    const float* Wk = (const float*)d_in[2];
    const float* Wv = (const float*)d_in[3];
    const float* Wo = (const float*)d_in[4];
    float* out = (float*)d_out;

    float *Q, *K, *V;
    __nv_bfloat16 *xh, *xl, *Ah, *Al, *Wh, *Wl;
    cudaGetSymbolAddress((void**)&Q,  g_Q);
    cudaGetSymbolAddress((void**)&K,  g_K);
    cudaGetSymbolAddress((void**)&V,  g_V);
    cudaGetSymbolAddress((void**)&xh, g_xh);
    cudaGetSymbolAddress((void**)&xl, g_xl);
    cudaGetSymbolAddress((void**)&Ah, g_Ah);
    cudaGetSymbolAddress((void**)&Al, g_Al);
    cudaGetSymbolAddress((void**)&Wh, g_Wh);
    cudaGetSymbolAddress((void**)&Wl, g_Wl);

    static bool attr_done = false;
    if (!attr_done) {
        cudaFuncSetAttribute(gemm_bf16x3, cudaFuncAttributeMaxDynamicSharedMemorySize, GEMM_SMEM);
        attr_done = true;
    }

    // split inputs
    split_kernel<<<(NROWS * DD / 4 + 255) / 256, 256>>>(x, xh, xl, NROWS * DD / 4);
    const int wn4 = DD * DD / 4;
    split_kernel<<<(wn4 + 255) / 256, 256>>>(Wq, Wh + 0 * DD * DD, Wl + 0 * DD * DD, wn4);
    split_kernel<<<(wn4 + 255) / 256, 256>>>(Wk, Wh + 1 * DD * DD, Wl + 1 * DD * DD, wn4);
    split_kernel<<<(wn4 + 255) / 256, 256>>>(Wv, Wh + 2 * DD * DD, Wl + 2 * DD * DD, wn4);
    split_kernel<<<(wn4 + 255) / 256, 256>>>(Wo, Wh + 3 * DD * DD, Wl + 3 * DD * DD, wn4);

    dim3 ggrid(DD / 128, NROWS / 128);   // (8, 32)
    gemm_bf16x3<<<ggrid, 256, GEMM_SMEM>>>(xh, xl, Wh + 0 * DD * DD, Wl + 0 * DD * DD, Q);
    gemm_bf16x3<<<ggrid, 256, GEMM_SMEM>>>(xh, xl, Wh + 1 * DD * DD, Wl + 1 * DD * DD, K);
    gemm_bf16x3<<<ggrid, 256, GEMM_SMEM>>>(xh, xl, Wh + 2 * DD * DD, Wl + 2 * DD * DD, V);

    attn_kernel<<<dim3(TT / 64, HH, BB), 128>>>(Q, K, V, Ah, Al);

    gemm_bf16x3<<<ggrid, 256, GEMM_SMEM>>>(Ah, Al, Wh + 3 * DD * DD, Wl + 3 * DD * DD, out);
}

// round 5
// speedup vs baseline: 3.1767x; 1.2968x over previous
#include <cuda_runtime.h>
#include <cuda_bf16.h>
#include <cstdint>

#define BB 2
#define TT 2048
#define DD 1024
#define HH 16
#define DHH 64
#define NROWS (BB*TT)   // 4096

// Scratch (allocation-free rule: __device__ globals)
__device__ __nv_bfloat16 g_Qh[NROWS*DD];
__device__ __nv_bfloat16 g_Ql[NROWS*DD];
__device__ __nv_bfloat16 g_Kh[NROWS*DD];
__device__ __nv_bfloat16 g_Kl[NROWS*DD];
__device__ __nv_bfloat16 g_Vh[NROWS*DD];
__device__ __nv_bfloat16 g_Vl[NROWS*DD];
__device__ __nv_bfloat16 g_xh[NROWS*DD];
__device__ __nv_bfloat16 g_xl[NROWS*DD];
__device__ __nv_bfloat16 g_Ah[NROWS*DD];
__device__ __nv_bfloat16 g_Al[NROWS*DD];
__device__ __nv_bfloat16 g_Wh[4*DD*DD];
__device__ __nv_bfloat16 g_Wl[4*DD*DD];

// ---------------------------------------------------------------------------
// helpers (portable PTX: cp.async / ldmatrix / mma.sync)
// ---------------------------------------------------------------------------
__device__ __forceinline__ uint32_t smem_u32(const void* p) {
    uint32_t a;
    asm("{ .reg .u64 t; cvta.to.shared.u64 t, %1; cvt.u32.u64 %0, t; }" : "=r"(a) : "l"(p));
    return a;
}
__device__ __forceinline__ void cp16(uint32_t dst, const void* src) {
    asm volatile("cp.async.cg.shared.global [%0], [%1], 16;" :: "r"(dst), "l"(src));
}
#define CP_COMMIT() asm volatile("cp.async.commit_group;" ::: "memory")
#define CP_WAIT(n)  asm volatile("cp.async.wait_group %0;" :: "n"(n) : "memory")

__device__ __forceinline__ void ldm_x4(uint32_t* r, uint32_t addr) {
    asm volatile("ldmatrix.sync.aligned.m8n8.x4.shared.b16 {%0,%1,%2,%3}, [%4];"
                 : "=r"(r[0]), "=r"(r[1]), "=r"(r[2]), "=r"(r[3]) : "r"(addr));
}
__device__ __forceinline__ void ldm_x4_t(uint32_t* r, uint32_t addr) {
    asm volatile("ldmatrix.sync.aligned.m8n8.x4.trans.shared.b16 {%0,%1,%2,%3}, [%4];"
                 : "=r"(r[0]), "=r"(r[1]), "=r"(r[2]), "=r"(r[3]) : "r"(addr));
}
__device__ __forceinline__ void mma_bf16(float* d, const uint32_t* a, uint32_t b0, uint32_t b1) {
    asm volatile(
        "mma.sync.aligned.m16n8k16.row.col.f32.bf16.bf16.f32 "
        "{%0,%1,%2,%3}, {%4,%5,%6,%7}, {%8,%9}, {%0,%1,%2,%3};"
        : "+f"(d[0]), "+f"(d[1]), "+f"(d[2]), "+f"(d[3])
        : "r"(a[0]), "r"(a[1]), "r"(a[2]), "r"(a[3]), "r"(b0), "r"(b1));
}
__device__ __forceinline__ uint32_t pack_bf16(float lo, float hi) {
    __nv_bfloat162 t = __halves2bfloat162(__float2bfloat16(lo), __float2bfloat16(hi));
    return *(uint32_t*)&t;
}

// ---------------------------------------------------------------------------
// split fp32 -> (bf16 hi, bf16 lo)
// ---------------------------------------------------------------------------
__global__ void __launch_bounds__(256) split_kernel(const float* __restrict__ in,
                                                    __nv_bfloat16* __restrict__ hi,
                                                    __nv_bfloat16* __restrict__ lo,
                                                    int n4) {
    int i = blockIdx.x * blockDim.x + threadIdx.x;
    if (i >= n4) return;
    float4 v = ((const float4*)in)[i];
    __align__(8) __nv_bfloat16 h[4], l[4];
    h[0] = __float2bfloat16(v.x); l[0] = __float2bfloat16(v.x - __bfloat162float(h[0]));
    h[1] = __float2bfloat16(v.y); l[1] = __float2bfloat16(v.y - __bfloat162float(h[1]));
    h[2] = __float2bfloat16(v.z); l[2] = __float2bfloat16(v.z - __bfloat162float(h[2]));
    h[3] = __float2bfloat16(v.w); l[3] = __float2bfloat16(v.w - __bfloat162float(h[3]));
    ((uint2*)hi)[i] = *(const uint2*)h;
    ((uint2*)lo)[i] = *(const uint2*)l;
}

// ---------------------------------------------------------------------------
// GEMM: C[n,m] = sum_k A[n,k]*B[m,k], bf16x3, mma.sync m16n8k16.
// CTA 128x128, BK=32, 3-stage cp.async, 8 warps (4m x 2n), warp tile 32x64.
// Output: fp32 (Cf) OR bf16 hi/lo pair (Ch/Cl) when Cf == nullptr.
// ---------------------------------------------------------------------------
#define NSTAGE 3
#define STG 32768
#define GEMM_SMEM (NSTAGE * STG)

__global__ void __launch_bounds__(256, 1) gemm_bf16x3(
    const __nv_bfloat16* __restrict__ Ahg, const __nv_bfloat16* __restrict__ Alg,
    const __nv_bfloat16* __restrict__ Bhg, const __nv_bfloat16* __restrict__ Blg,
    float* __restrict__ Cf,
    __nv_bfloat16* __restrict__ Ch, __nv_bfloat16* __restrict__ Cl) {
    extern __shared__ __align__(128) char smem[];
    const uint32_t sbase = smem_u32(smem);
    const int tid  = threadIdx.x;
    const int wid  = tid >> 5;
    const int lane = tid & 31;
    const int n0 = blockIdx.y * 128;
    const int m0 = blockIdx.x * 128;

    const int warp_m = (wid & 3) * 32;
    const int warp_n = (wid >> 2) * 64;

    const int KT = DD / 32;

    const int lrow = tid >> 1;
    const int lc0  = (tid & 1) * 2;
    auto load_stage = [&](int s) {
        const int k0 = s * 32;
        const uint32_t stg = sbase + (uint32_t)(s % NSTAGE) * STG;
        #pragma unroll
        for (int cc = 0; cc < 2; cc++) {
            const int c = lc0 + cc;
            const uint32_t d = (uint32_t)(lrow * 64 + ((c ^ ((lrow >> 1) & 3)) * 16));
            const size_t sa = (size_t)(n0 + lrow) * DD + k0 + c * 8;
            const size_t sb = (size_t)(m0 + lrow) * DD + k0 + c * 8;
            cp16(stg + 0     + d, Ahg + sa);
            cp16(stg + 8192  + d, Alg + sa);
            cp16(stg + 16384 + d, Bhg + sb);
            cp16(stg + 24576 + d, Blg + sb);
        }
        CP_COMMIT();
    };

    load_stage(0);
    load_stage(1);
    load_stage(2);

    float acc[2][8][4];
    #pragma unroll
    for (int mt = 0; mt < 2; mt++)
        #pragma unroll
        for (int nt = 0; nt < 8; nt++)
            #pragma unroll
            for (int i = 0; i < 4; i++) acc[mt][nt][i] = 0.0f;

    const int a_r    = (lane & 15);
    const int a_csel = (lane >> 4);
    const int b_g    = (lane >> 3);
    const int b_r    = ((b_g >> 1) << 3) + (lane & 7);
    const int b_csel = (b_g & 1);

    for (int s = 0; s < KT; s++) {
        CP_WAIT(NSTAGE - 1);
        __syncthreads();

        const uint32_t stg = sbase + (uint32_t)(s % NSTAGE) * STG;
        #pragma unroll
        for (int kk = 0; kk < 32; kk += 16) {
            const int cbase = kk >> 3;
            uint32_t ah[2][4], al[2][4], bh[4][4], bl[4][4];
            #pragma unroll
            for (int mt = 0; mt < 2; mt++) {
                const int r = warp_m + mt * 16 + a_r;
                const int c = (cbase + a_csel) ^ ((r >> 1) & 3);
                const uint32_t ad = (uint32_t)(r * 64 + c * 16);
                ldm_x4(ah[mt], stg + 0    + ad);
                ldm_x4(al[mt], stg + 8192 + ad);
            }
            #pragma unroll
            for (int nt4 = 0; nt4 < 4; nt4++) {
                const int r = warp_n + nt4 * 16 + b_r;
                const int c = (cbase + b_csel) ^ ((r >> 1) & 3);
                const uint32_t bd = (uint32_t)(r * 64 + c * 16);
                ldm_x4(bh[nt4], stg + 16384 + bd);
                ldm_x4(bl[nt4], stg + 24576 + bd);
            }
            #pragma unroll
            for (int mt = 0; mt < 2; mt++)
                #pragma unroll
                for (int nt = 0; nt < 8; nt++) {
                    const uint32_t bh0 = bh[nt >> 1][(nt & 1) * 2];
                    const uint32_t bh1 = bh[nt >> 1][(nt & 1) * 2 + 1];
                    const uint32_t bl0 = bl[nt >> 1][(nt & 1) * 2];
                    const uint32_t bl1 = bl[nt >> 1][(nt & 1) * 2 + 1];
                    mma_bf16(acc[mt][nt], ah[mt], bh0, bh1);
                    mma_bf16(acc[mt][nt], al[mt], bh0, bh1);
                    mma_bf16(acc[mt][nt], ah[mt], bl0, bl1);
                }
        }
        __syncthreads();
        if (s + NSTAGE < KT) load_stage(s + NSTAGE);
        else                 CP_COMMIT();
    }

    #pragma unroll
    for (int mt = 0; mt < 2; mt++)
        #pragma unroll
        for (int nt = 0; nt < 8; nt++) {
            const int r   = n0 + warp_m + mt * 16 + (lane >> 2);
            const int col = m0 + warp_n + nt * 8 + (lane & 3) * 2;
            if (Cf) {
                float2 v0 = {acc[mt][nt][0], acc[mt][nt][1]};
                float2 v1 = {acc[mt][nt][2], acc[mt][nt][3]};
                *(float2*)(Cf + (size_t)r * DD + col)       = v0;
                *(float2*)(Cf + (size_t)(r + 8) * DD + col) = v1;
            } else {
                #pragma unroll
                for (int h2 = 0; h2 < 2; h2++) {
                    float v0 = acc[mt][nt][2 * h2], v1 = acc[mt][nt][2 * h2 + 1];
                    float h0 = __bfloat162float(__float2bfloat16(v0));
                    float h1 = __bfloat162float(__float2bfloat16(v1));
                    size_t o = (size_t)(r + 8 * h2) * DD + col;
                    *(uint32_t*)(Ch + o) = pack_bf16(h0, h1);
                    *(uint32_t*)(Cl + o) = pack_bf16(v0 - h0, v1 - h1);
                }
            }
        }
}

// ---------------------------------------------------------------------------
// Tensor-core sliding-window flash attention (bf16x3).
// CTA: 64 queries of one (b,h); 4 warps, warp = 16 queries x 64 keys.
// Window: key in [i-128, i]. K/V chunks of 64 keys, double-buffered cp.async.
// smem tiles: 64 rows x 64 bf16 (128B rows), chunk swizzle cd ^= (r&7).
// ---------------------------------------------------------------------------
#define ATTN_SMEM (16384 + 2*32768)   // Q(h,l) 16K + 2 x KV(h,l) 32K = 80K

__global__ void __launch_bounds__(128, 2) attn_tc(
    const __nv_bfloat16* __restrict__ Qh, const __nv_bfloat16* __restrict__ Ql,
    const __nv_bfloat16* __restrict__ Kh, const __nv_bfloat16* __restrict__ Kl,
    const __nv_bfloat16* __restrict__ Vh, const __nv_bfloat16* __restrict__ Vl,
    __nv_bfloat16* __restrict__ Ah, __nv_bfloat16* __restrict__ Al) {
    extern __shared__ __align__(128) char smem[];
    const uint32_t sb = smem_u32(smem);
    const int tid = threadIdx.x;
    const int lane = tid & 31;
    const int w = tid >> 5;
    const int q0 = blockIdx.x * 64;
    const int h = blockIdx.y;
    const int b = blockIdx.z;
    const size_t rowbase = (size_t)b * TT;
    const int col0 = h * DHH;

    const uint32_t QH_ = sb, QL_ = sb + 8192;
    auto KH_ = [&](int buf) { return sb + 16384 + (uint32_t)buf * 32768; };

    auto toff = [](int r, int cd) { return (uint32_t)(r * 128 + ((cd ^ (r & 7)) << 4)); };

    // loaders: thread -> row tid>>1, 4 chunks of 16B
    const int lr = tid >> 1;
    const int lc0 = (tid & 1) * 4;
    auto load_q = [&]() {
        const size_t g = (rowbase + q0 + lr) * DD + col0;
        #pragma unroll
        for (int c = 0; c < 4; c++) {
            const int cd = lc0 + c;
            cp16(QH_ + toff(lr, cd), Qh + g + cd * 8);
            cp16(QL_ + toff(lr, cd), Ql + g + cd * 8);
        }
    };
    auto load_kv = [&](int c, int buf) {
        const size_t g = (rowbase + c * 64 + lr) * DD + col0;
        const uint32_t base = KH_(buf);
        #pragma unroll
        for (int cc = 0; cc < 4; cc++) {
            const int cd = lc0 + cc;
            const uint32_t d = toff(lr, cd);
            cp16(base + 0     + d, Kh + g + cd * 8);
            cp16(base + 8192  + d, Kl + g + cd * 8);
            cp16(base + 16384 + d, Vh + g + cd * 8);
            cp16(base + 24576 + d, Vl + g + cd * 8);
        }
    };

    const int c_lo = (q0 >= 128) ? ((q0 - 128) >> 6) : 0;
    const int c_hi = q0 >> 6;

    load_q();
    load_kv(c_lo, c_lo & 1);
    CP_COMMIT();

    float m[2] = {-1e30f, -1e30f}, l[2] = {0.0f, 0.0f};
    float accO[8][4];
    #pragma unroll
    for (int nt = 0; nt < 8; nt++)
        #pragma unroll
        for (int i = 0; i < 4; i++) accO[nt][i] = 0.0f;

    uint32_t qhf[4][4], qlf[4][4];
    bool qloaded = false;

    const int row_in_warp = lane >> 2;   // + 8*h2
    const int colpair = (lane & 3) * 2;

    for (int c = c_lo; c <= c_hi; c++) {
        const int buf = c & 1;
        if (c < c_hi) { load_kv(c + 1, (c + 1) & 1); CP_COMMIT(); CP_WAIT(1); }
        else          { CP_WAIT(0); }
        __syncthreads();

        if (!qloaded) {
            qloaded = true;
            #pragma unroll
            for (int ks = 0; ks < 4; ks++) {
                const int r = w * 16 + (lane & 15);
                const int cd = 2 * ks + (lane >> 4);
                ldm_x4(qhf[ks], QH_ + toff(r, cd));
                ldm_x4(qlf[ks], QL_ + toff(r, cd));
            }
        }

        // ---- S = Q K^T (bf16x3) ----
        float sacc[8][4];
        #pragma unroll
        for (int nt = 0; nt < 8; nt++)
            #pragma unroll
            for (int i = 0; i < 4; i++) sacc[nt][i] = 0.0f;

        const uint32_t kh_base = KH_(buf), kl_base = kh_base + 8192;
        const int krow = (lane & 7) + ((lane & 16) >> 1);   // row within n16 group
        const int kcd0 = (lane >> 3) & 1;
        #pragma unroll
        for (int ks = 0; ks < 4; ks++) {
            #pragma unroll
            for (int ng = 0; ng < 4; ng++) {
                const int rn = ng * 16 + krow;
                const int cd = 2 * ks + kcd0;
                uint32_t bh[4], bl[4];
                ldm_x4(bh, kh_base + toff(rn, cd));
                ldm_x4(bl, kl_base + toff(rn, cd));
                mma_bf16(sacc[2*ng],   qhf[ks], bh[0], bh[1]);
                mma_bf16(sacc[2*ng],   qlf[ks], bh[0], bh[1]);
                mma_bf16(sacc[2*ng],   qhf[ks], bl[0], bl[1]);
                mma_bf16(sacc[2*ng+1], qhf[ks], bh[2], bh[3]);
                mma_bf16(sacc[2*ng+1], qlf[ks], bh[2], bh[3]);
                mma_bf16(sacc[2*ng+1], qhf[ks], bl[2], bl[3]);
            }
        }

        // ---- mask + scale + online softmax ----
        const int kbase = c * 64;
        float rmax[2] = {-1e30f, -1e30f};
        #pragma unroll
        for (int nt = 0; nt < 8; nt++)
            #pragma unroll
            for (int e2 = 0; e2 < 4; e2++) {
                const int h2 = e2 >> 1;
                const int key = kbase + nt * 8 + colpair + (e2 & 1);
                const int iq  = q0 + w * 16 + row_in_warp + 8 * h2;
                float s = sacc[nt][e2] * 0.125f;
                s = (key <= iq && key + 128 >= iq) ? s : -1e30f;
                sacc[nt][e2] = s;
                rmax[h2] = fmaxf(rmax[h2], s);
            }
        #pragma unroll
        for (int h2 = 0; h2 < 2; h2++) {
            rmax[h2] = fmaxf(rmax[h2], __shfl_xor_sync(0xffffffffu, rmax[h2], 1));
            rmax[h2] = fmaxf(rmax[h2], __shfl_xor_sync(0xffffffffu, rmax[h2], 2));
        }
        float corr[2], rsum[2] = {0.0f, 0.0f};
        #pragma unroll
        for (int h2 = 0; h2 < 2; h2++) {
            const float newm = fmaxf(m[h2], rmax[h2]);
            corr[h2] = __expf(m[h2] - newm);
            m[h2] = newm;
        }
        #pragma unroll
        for (int nt = 0; nt < 8; nt++)
            #pragma unroll
            for (int e2 = 0; e2 < 4; e2++) {
                const int h2 = e2 >> 1;
                const float p = __expf(sacc[nt][e2] - m[h2]);
                sacc[nt][e2] = p;
                rsum[h2] += p;
            }
        #pragma unroll
        for (int h2 = 0; h2 < 2; h2++) {
            rsum[h2] += __shfl_xor_sync(0xffffffffu, rsum[h2], 1);
            rsum[h2] += __shfl_xor_sync(0xffffffffu, rsum[h2], 2);
            l[h2] = l[h2] * corr[h2] + rsum[h2];
        }
        #pragma unroll
        for (int nt = 0; nt < 8; nt++) {
            accO[nt][0] *= corr[0]; accO[nt][1] *= corr[0];
            accO[nt][2] *= corr[1]; accO[nt][3] *= corr[1];
        }

        // ---- P fragments (registers, hi/lo split) ----
        uint32_t ph[4][4], pl[4][4];
        #pragma unroll
        for (int js = 0; js < 4; js++) {
            #pragma unroll
            for (int half16 = 0; half16 < 2; half16++) {   // which n8-tile of S -> k half
                const int nt = 2 * js + half16;
                #pragma unroll
                for (int h2 = 0; h2 < 2; h2++) {
                    const float p0 = sacc[nt][2 * h2], p1 = sacc[nt][2 * h2 + 1];
                    const float h0 = __bfloat162float(__float2bfloat16(p0));
                    const float h1 = __bfloat162float(__float2bfloat16(p1));
                    ph[js][half16 * 2 + h2] = pack_bf16(h0, h1);
                    pl[js][half16 * 2 + h2] = pack_bf16(p0 - h0, p1 - h1);
                }
            }
        }

        // ---- O += P V (bf16x3, V via ldmatrix.trans) ----
        const uint32_t vh_base = KH_(buf) + 16384, vl_base = vh_base + 8192;
        const int vrow = (lane & 7) + (lane & 8);
        const int vcd0 = lane >> 4;
        #pragma unroll
        for (int js = 0; js < 4; js++) {
            #pragma unroll
            for (int ng = 0; ng < 4; ng++) {
                const int rv = js * 16 + vrow;
                const int cd = 2 * ng + vcd0;
                uint32_t vhf[4], vlf[4];
                ldm_x4_t(vhf, vh_base + toff(rv, cd));
                ldm_x4_t(vlf, vl_base + toff(rv, cd));
                mma_bf16(accO[2*ng],   ph[js], vhf[0], vhf[1]);
                mma_bf16(accO[2*ng],   pl[js], vhf[0], vhf[1]);
                mma_bf16(accO[2*ng],   ph[js], vlf[0], vlf[1]);
                mma_bf16(accO[2*ng+1], ph[js], vhf[2], vhf[3]);
                mma_bf16(accO[2*ng+1], pl[js], vhf[2], vhf[3]);
                mma_bf16(accO[2*ng+1], ph[js], vlf[2], vlf[3]);
            }
        }
        __syncthreads();
    }

    // ---- write O (bf16 hi/lo) ----
    const float inv0 = 1.0f / l[0], inv1 = 1.0f / l[1];
    #pragma unroll
    for (int nt = 0; nt < 8; nt++) {
        #pragma unroll
        for (int h2 = 0; h2 < 2; h2++) {
            const float inv = h2 ? inv1 : inv0;
            const int gi = q0 + w * 16 + row_in_warp + 8 * h2;
            const size_t o = (rowbase + gi) * DD + col0 + nt * 8 + colpair;
            const float v0 = accO[nt][2 * h2] * inv, v1 = accO[nt][2 * h2 + 1] * inv;
            const float h0 = __bfloat162float(__float2bfloat16(v0));
            const float h1 = __bfloat162float(__float2bfloat16(v1));
            *(uint32_t*)(Ah + o) = pack_bf16(h0, h1);
            *(uint32_t*)(Al + o) = pack_bf16(v0 - h0, v1 - h1);
        }
    }
}

// ---------------------------------------------------------------------------
extern "C" void kernel_launch(void* const* d_in, const int* in_sizes, int n_in,
                              void* d_out, int out_size) {
    const float* x  = (const float*)d_in[0];
    const float* Wq = (const float*)d_in[1];
    const float* Wk = (const float*)d_in[2];
    const float* Wv = (const float*)d_in[3];
    const float* Wo = (const float*)d_in[4];
    float* out = (float*)d_out;

    __nv_bfloat16 *Qh, *Ql, *Kh, *Kl, *Vh, *Vl, *xh, *xl, *Ah, *Al, *Wh, *Wl;
    cudaGetSymbolAddress((void**)&Qh, g_Qh);
    cudaGetSymbolAddress((void**)&Ql, g_Ql);
    cudaGetSymbolAddress((void**)&Kh, g_Kh);
    cudaGetSymbolAddress((void**)&Kl, g_Kl);
    cudaGetSymbolAddress((void**)&Vh, g_Vh);
    cudaGetSymbolAddress((void**)&Vl, g_Vl);
    cudaGetSymbolAddress((void**)&xh, g_xh);
    cudaGetSymbolAddress((void**)&xl, g_xl);
    cudaGetSymbolAddress((void**)&Ah, g_Ah);
    cudaGetSymbolAddress((void**)&Al, g_Al);
    cudaGetSymbolAddress((void**)&Wh, g_Wh);
    cudaGetSymbolAddress((void**)&Wl, g_Wl);

    static bool attr_done = false;
    if (!attr_done) {
        cudaFuncSetAttribute(gemm_bf16x3, cudaFuncAttributeMaxDynamicSharedMemorySize, GEMM_SMEM);
        cudaFuncSetAttribute(attn_tc, cudaFuncAttributeMaxDynamicSharedMemorySize, ATTN_SMEM);
        attr_done = true;
    }

    // split inputs
    split_kernel<<<(NROWS * DD / 4 + 255) / 256, 256>>>(x, xh, xl, NROWS * DD / 4);
    const int wn4 = DD * DD / 4;
    split_kernel<<<(wn4 + 255) / 256, 256>>>(Wq, Wh + 0 * DD * DD, Wl + 0 * DD * DD, wn4);
    split_kernel<<<(wn4 + 255) / 256, 256>>>(Wk, Wh + 1 * DD * DD, Wl + 1 * DD * DD, wn4);
    split_kernel<<<(wn4 + 255) / 256, 256>>>(Wv, Wh + 2 * DD * DD, Wl + 2 * DD * DD, wn4);
    split_kernel<<<(wn4 + 255) / 256, 256>>>(Wo, Wh + 3 * DD * DD, Wl + 3 * DD * DD, wn4);

    dim3 ggrid(DD / 128, NROWS / 128);   // (8, 32)
    gemm_bf16x3<<<ggrid, 256, GEMM_SMEM>>>(xh, xl, Wh + 0 * DD * DD, Wl + 0 * DD * DD,
                                           nullptr, Qh, Ql);
    gemm_bf16x3<<<ggrid, 256, GEMM_SMEM>>>(xh, xl, Wh + 1 * DD * DD, Wl + 1 * DD * DD,
                                           nullptr, Kh, Kl);
    gemm_bf16x3<<<ggrid, 256, GEMM_SMEM>>>(xh, xl, Wh + 2 * DD * DD, Wl + 2 * DD * DD,
                                           nullptr, Vh, Vl);

    attn_tc<<<dim3(TT / 64, HH, BB), 128, ATTN_SMEM>>>(Qh, Ql, Kh, Kl, Vh, Vl, Ah, Al);

    gemm_bf16x3<<<ggrid, 256, GEMM_SMEM>>>(Ah, Al, Wh + 3 * DD * DD, Wl + 3 * DD * DD,
                                           out, nullptr, nullptr);
}

// round 6
// speedup vs baseline: 3.2388x; 1.0196x over previous
#include <cuda_runtime.h>
#include <cuda_fp16.h>
#include <cstdint>

#define BB 2
#define TT 2048
#define DD 1024
#define HH 16
#define DHH 64
#define NROWS (BB*TT)   // 4096

// Scratch (allocation-free rule: __device__ globals)
__device__ __half g_Qh[NROWS*DD];
__device__ __half g_Ql[NROWS*DD];
__device__ __half g_Kh[NROWS*DD];
__device__ __half g_Vh[NROWS*DD];
__device__ __half g_xh[NROWS*DD];
__device__ __half g_xl[NROWS*DD];
__device__ __half g_Ah[NROWS*DD];
__device__ __half g_Al[NROWS*DD];
__device__ __half g_W[4*DD*DD];

// ---------------------------------------------------------------------------
// helpers (portable PTX: cp.async / ldmatrix / mma.sync)
// ---------------------------------------------------------------------------
__device__ __forceinline__ uint32_t smem_u32(const void* p) {
    uint32_t a;
    asm("{ .reg .u64 t; cvta.to.shared.u64 t, %1; cvt.u32.u64 %0, t; }" : "=r"(a) : "l"(p));
    return a;
}
__device__ __forceinline__ void cp16(uint32_t dst, const void* src) {
    asm volatile("cp.async.cg.shared.global [%0], [%1], 16;" :: "r"(dst), "l"(src));
}
#define CP_COMMIT() asm volatile("cp.async.commit_group;" ::: "memory")
#define CP_WAIT(n)  asm volatile("cp.async.wait_group %0;" :: "n"(n) : "memory")

__device__ __forceinline__ void ldm_x4(uint32_t* r, uint32_t addr) {
    asm volatile("ldmatrix.sync.aligned.m8n8.x4.shared.b16 {%0,%1,%2,%3}, [%4];"
                 : "=r"(r[0]), "=r"(r[1]), "=r"(r[2]), "=r"(r[3]) : "r"(addr));
}
__device__ __forceinline__ void ldm_x4_t(uint32_t* r, uint32_t addr) {
    asm volatile("ldmatrix.sync.aligned.m8n8.x4.trans.shared.b16 {%0,%1,%2,%3}, [%4];"
                 : "=r"(r[0]), "=r"(r[1]), "=r"(r[2]), "=r"(r[3]) : "r"(addr));
}
__device__ __forceinline__ void mma_f16(float* d, const uint32_t* a, uint32_t b0, uint32_t b1) {
    asm volatile(
        "mma.sync.aligned.m16n8k16.row.col.f32.f16.f16.f32 "
        "{%0,%1,%2,%3}, {%4,%5,%6,%7}, {%8,%9}, {%0,%1,%2,%3};"
        : "+f"(d[0]), "+f"(d[1]), "+f"(d[2]), "+f"(d[3])
        : "r"(a[0]), "r"(a[1]), "r"(a[2]), "r"(a[3]), "r"(b0), "r"(b1));
}
__device__ __forceinline__ uint32_t pack_f16(float lo, float hi) {
    __half2 t = __halves2half2(__float2half(lo), __float2half(hi));
    return *(uint32_t*)&t;
}

// ---------------------------------------------------------------------------
// split fp32 -> (fp16 hi, fp16 lo) ; cvt fp32 -> fp16
// ---------------------------------------------------------------------------
__global__ void __launch_bounds__(256) split16(const float* __restrict__ in,
                                               __half* __restrict__ hi,
                                               __half* __restrict__ lo, int n4) {
    int i = blockIdx.x * blockDim.x + threadIdx.x;
    if (i >= n4) return;
    float4 v = ((const float4*)in)[i];
    __align__(8) __half h[4], l[4];
    h[0] = __float2half(v.x); l[0] = __float2half(v.x - __half2float(h[0]));
    h[1] = __float2half(v.y); l[1] = __float2half(v.y - __half2float(h[1]));
    h[2] = __float2half(v.z); l[2] = __float2half(v.z - __half2float(h[2]));
    h[3] = __float2half(v.w); l[3] = __float2half(v.w - __half2float(h[3]));
    ((uint2*)hi)[i] = *(const uint2*)h;
    ((uint2*)lo)[i] = *(const uint2*)l;
}
__global__ void __launch_bounds__(256) cvt16(const float* __restrict__ in,
                                             __half* __restrict__ out, int n4) {
    int i = blockIdx.x * blockDim.x + threadIdx.x;
    if (i >= n4) return;
    float4 v = ((const float4*)in)[i];
    __align__(8) __half h[4];
    h[0] = __float2half(v.x); h[1] = __float2half(v.y);
    h[2] = __float2half(v.z); h[3] = __float2half(v.w);
    ((uint2*)out)[i] = *(const uint2*)h;
}

// ---------------------------------------------------------------------------
// GEMM: C[n,m] = sum_k A[n,k]*B[m,k], fp16x2 (A split hi/lo, B plain fp16).
// CTA 128x128, BK=32, 3-stage cp.async, 8 warps (4m x 2n), warp tile 32x64.
// Epilogue: fp32 (Cf) | fp16 hi/lo (Ch+Cl) | fp16 single (Ch).
// Stage layout (24KB): Ah +0, Al +8192, B +16384.
// ---------------------------------------------------------------------------
#define NSTAGE 3
#define STG 24576
#define GEMM_SMEM (NSTAGE * STG)

__global__ void __launch_bounds__(256, 1) gemm_f16x2(
    const __half* __restrict__ Ahg, const __half* __restrict__ Alg,
    const __half* __restrict__ Bg,
    float* __restrict__ Cf,
    __half* __restrict__ Ch, __half* __restrict__ Cl) {
    extern __shared__ __align__(128) char smem[];
    const uint32_t sbase = smem_u32(smem);
    const int tid  = threadIdx.x;
    const int wid  = tid >> 5;
    const int lane = tid & 31;
    const int n0 = blockIdx.y * 128;
    const int m0 = blockIdx.x * 128;

    const int warp_m = (wid & 3) * 32;
    const int warp_n = (wid >> 2) * 64;

    const int KT = DD / 32;

    const int lrow = tid >> 1;
    const int lc0  = (tid & 1) * 2;
    auto load_stage = [&](int s) {
        const int k0 = s * 32;
        const uint32_t stg = sbase + (uint32_t)(s % NSTAGE) * STG;
        #pragma unroll
        for (int cc = 0; cc < 2; cc++) {
            const int c = lc0 + cc;
            const uint32_t d = (uint32_t)(lrow * 64 + ((c ^ ((lrow >> 1) & 3)) * 16));
            const size_t sa = (size_t)(n0 + lrow) * DD + k0 + c * 8;
            const size_t sb = (size_t)(m0 + lrow) * DD + k0 + c * 8;
            cp16(stg + 0     + d, Ahg + sa);
            cp16(stg + 8192  + d, Alg + sa);
            cp16(stg + 16384 + d, Bg  + sb);
        }
        CP_COMMIT();
    };

    load_stage(0);
    load_stage(1);
    load_stage(2);

    float acc[2][8][4];
    #pragma unroll
    for (int mt = 0; mt < 2; mt++)
        #pragma unroll
        for (int nt = 0; nt < 8; nt++)
            #pragma unroll
            for (int i = 0; i < 4; i++) acc[mt][nt][i] = 0.0f;

    const int a_r    = (lane & 15);
    const int a_csel = (lane >> 4);
    const int b_g    = (lane >> 3);
    const int b_r    = ((b_g >> 1) << 3) + (lane & 7);
    const int b_csel = (b_g & 1);

    for (int s = 0; s < KT; s++) {
        CP_WAIT(NSTAGE - 1);
        __syncthreads();

        const uint32_t stg = sbase + (uint32_t)(s % NSTAGE) * STG;
        #pragma unroll
        for (int kk = 0; kk < 32; kk += 16) {
            const int cbase = kk >> 3;
            uint32_t ah[2][4], al[2][4], bh[4][4];
            #pragma unroll
            for (int mt = 0; mt < 2; mt++) {
                const int r = warp_m + mt * 16 + a_r;
                const int c = (cbase + a_csel) ^ ((r >> 1) & 3);
                const uint32_t ad = (uint32_t)(r * 64 + c * 16);
                ldm_x4(ah[mt], stg + 0    + ad);
                ldm_x4(al[mt], stg + 8192 + ad);
            }
            #pragma unroll
            for (int nt4 = 0; nt4 < 4; nt4++) {
                const int r = warp_n + nt4 * 16 + b_r;
                const int c = (cbase + b_csel) ^ ((r >> 1) & 3);
                ldm_x4(bh[nt4], stg + 16384 + (uint32_t)(r * 64 + c * 16));
            }
            #pragma unroll
            for (int mt = 0; mt < 2; mt++)
                #pragma unroll
                for (int nt = 0; nt < 8; nt++) {
                    const uint32_t b0 = bh[nt >> 1][(nt & 1) * 2];
                    const uint32_t b1 = bh[nt >> 1][(nt & 1) * 2 + 1];
                    mma_f16(acc[mt][nt], ah[mt], b0, b1);
                    mma_f16(acc[mt][nt], al[mt], b0, b1);
                }
        }
        __syncthreads();
        if (s + NSTAGE < KT) load_stage(s + NSTAGE);
        else                 CP_COMMIT();
    }

    #pragma unroll
    for (int mt = 0; mt < 2; mt++)
        #pragma unroll
        for (int nt = 0; nt < 8; nt++) {
            const int r   = n0 + warp_m + mt * 16 + (lane >> 2);
            const int col = m0 + warp_n + nt * 8 + (lane & 3) * 2;
            if (Cf) {
                float2 v0 = {acc[mt][nt][0], acc[mt][nt][1]};
                float2 v1 = {acc[mt][nt][2], acc[mt][nt][3]};
                *(float2*)(Cf + (size_t)r * DD + col)       = v0;
                *(float2*)(Cf + (size_t)(r + 8) * DD + col) = v1;
            } else if (Cl) {
                #pragma unroll
                for (int h2 = 0; h2 < 2; h2++) {
                    float v0 = acc[mt][nt][2 * h2], v1 = acc[mt][nt][2 * h2 + 1];
                    float h0 = __half2float(__float2half(v0));
                    float h1 = __half2float(__float2half(v1));
                    size_t o = (size_t)(r + 8 * h2) * DD + col;
                    *(uint32_t*)(Ch + o) = pack_f16(h0, h1);
                    *(uint32_t*)(Cl + o) = pack_f16(v0 - h0, v1 - h1);
                }
            } else {
                #pragma unroll
                for (int h2 = 0; h2 < 2; h2++) {
                    size_t o = (size_t)(r + 8 * h2) * DD + col;
                    *(uint32_t*)(Ch + o) = pack_f16(acc[mt][nt][2 * h2], acc[mt][nt][2 * h2 + 1]);
                }
            }
        }
}

// ---------------------------------------------------------------------------
// Tensor-core sliding-window flash attention (fp16x2: Q & P split, K/V plain).
// CTA: 64 queries x (b,h); 4 warps, warp = 16 queries x 64 keys.
// smem: Qh 8K, Ql 8K, then 2 bufs of (K 8K + V 8K). 48KB total.
// ---------------------------------------------------------------------------
#define ATTN_SMEM (16384 + 2*16384)

__global__ void __launch_bounds__(128, 2) attn_tc(
    const __half* __restrict__ Qh, const __half* __restrict__ Ql,
    const __half* __restrict__ Kh, const __half* __restrict__ Vh,
    __half* __restrict__ Ah, __half* __restrict__ Al) {
    extern __shared__ __align__(128) char smem[];
    const uint32_t sb = smem_u32(smem);
    const int tid = threadIdx.x;
    const int lane = tid & 31;
    const int w = tid >> 5;
    const int q0 = blockIdx.x * 64;
    const int h = blockIdx.y;
    const int b = blockIdx.z;
    const size_t rowbase = (size_t)b * TT;
    const int col0 = h * DHH;

    const uint32_t QH_ = sb, QL_ = sb + 8192;
    auto KV_ = [&](int buf) { return sb + 16384 + (uint32_t)buf * 16384; };

    auto toff = [](int r, int cd) { return (uint32_t)(r * 128 + ((cd ^ (r & 7)) << 4)); };

    const int lr = tid >> 1;
    const int lc0 = (tid & 1) * 4;
    auto load_q = [&]() {
        const size_t g = (rowbase + q0 + lr) * DD + col0;
        #pragma unroll
        for (int c = 0; c < 4; c++) {
            const int cd = lc0 + c;
            cp16(QH_ + toff(lr, cd), Qh + g + cd * 8);
            cp16(QL_ + toff(lr, cd), Ql + g + cd * 8);
        }
    };
    auto load_kv = [&](int c, int buf) {
        const size_t g = (rowbase + c * 64 + lr) * DD + col0;
        const uint32_t base = KV_(buf);
        #pragma unroll
        for (int cc = 0; cc < 4; cc++) {
            const int cd = lc0 + cc;
            const uint32_t d = toff(lr, cd);
            cp16(base + 0    + d, Kh + g + cd * 8);
            cp16(base + 8192 + d, Vh + g + cd * 8);
        }
    };

    const int c_lo = (q0 >= 128) ? ((q0 - 128) >> 6) : 0;
    const int c_hi = q0 >> 6;

    load_q();
    load_kv(c_lo, c_lo & 1);
    CP_COMMIT();

    float m[2] = {-1e30f, -1e30f}, l[2] = {0.0f, 0.0f};
    float accO[8][4];
    #pragma unroll
    for (int nt = 0; nt < 8; nt++)
        #pragma unroll
        for (int i = 0; i < 4; i++) accO[nt][i] = 0.0f;

    uint32_t qhf[4][4], qlf[4][4];
    bool qloaded = false;

    const int row_in_warp = lane >> 2;
    const int colpair = (lane & 3) * 2;

    for (int c = c_lo; c <= c_hi; c++) {
        const int buf = c & 1;
        if (c < c_hi) { load_kv(c + 1, (c + 1) & 1); CP_COMMIT(); CP_WAIT(1); }
        else          { CP_WAIT(0); }
        __syncthreads();

        if (!qloaded) {
            qloaded = true;
            #pragma unroll
            for (int ks = 0; ks < 4; ks++) {
                const int r = w * 16 + (lane & 15);
                const int cd = 2 * ks + (lane >> 4);
                ldm_x4(qhf[ks], QH_ + toff(r, cd));
                ldm_x4(qlf[ks], QL_ + toff(r, cd));
            }
        }

        // ---- S = Q K^T (fp16x2) ----
        float sacc[8][4];
        #pragma unroll
        for (int nt = 0; nt < 8; nt++)
            #pragma unroll
            for (int i = 0; i < 4; i++) sacc[nt][i] = 0.0f;

        const uint32_t kh_base = KV_(buf);
        const int krow = (lane & 7) + ((lane & 16) >> 1);
        const int kcd0 = (lane >> 3) & 1;
        #pragma unroll
        for (int ks = 0; ks < 4; ks++) {
            #pragma unroll
            for (int ng = 0; ng < 4; ng++) {
                const int rn = ng * 16 + krow;
                const int cd = 2 * ks + kcd0;
                uint32_t bh[4];
                ldm_x4(bh, kh_base + toff(rn, cd));
                mma_f16(sacc[2*ng],   qhf[ks], bh[0], bh[1]);
                mma_f16(sacc[2*ng],   qlf[ks], bh[0], bh[1]);
                mma_f16(sacc[2*ng+1], qhf[ks], bh[2], bh[3]);
                mma_f16(sacc[2*ng+1], qlf[ks], bh[2], bh[3]);
            }
        }

        // ---- mask + scale + online softmax ----
        const int kbase = c * 64;
        float rmax[2] = {-1e30f, -1e30f};
        #pragma unroll
        for (int nt = 0; nt < 8; nt++)
            #pragma unroll
            for (int e2 = 0; e2 < 4; e2++) {
                const int h2 = e2 >> 1;
                const int key = kbase + nt * 8 + colpair + (e2 & 1);
                const int iq  = q0 + w * 16 + row_in_warp + 8 * h2;
                float s = sacc[nt][e2] * 0.125f;
                s = (key <= iq && key + 128 >= iq) ? s : -1e30f;
                sacc[nt][e2] = s;
                rmax[h2] = fmaxf(rmax[h2], s);
            }
        #pragma unroll
        for (int h2 = 0; h2 < 2; h2++) {
            rmax[h2] = fmaxf(rmax[h2], __shfl_xor_sync(0xffffffffu, rmax[h2], 1));
            rmax[h2] = fmaxf(rmax[h2], __shfl_xor_sync(0xffffffffu, rmax[h2], 2));
        }
        float corr[2], rsum[2] = {0.0f, 0.0f};
        #pragma unroll
        for (int h2 = 0; h2 < 2; h2++) {
            const float newm = fmaxf(m[h2], rmax[h2]);
            corr[h2] = __expf(m[h2] - newm);
            m[h2] = newm;
        }
        #pragma unroll
        for (int nt = 0; nt < 8; nt++)
            #pragma unroll
            for (int e2 = 0; e2 < 4; e2++) {
                const int h2 = e2 >> 1;
                const float p = __expf(sacc[nt][e2] - m[h2]);
                sacc[nt][e2] = p;
                rsum[h2] += p;
            }
        #pragma unroll
        for (int h2 = 0; h2 < 2; h2++) {
            rsum[h2] += __shfl_xor_sync(0xffffffffu, rsum[h2], 1);
            rsum[h2] += __shfl_xor_sync(0xffffffffu, rsum[h2], 2);
            l[h2] = l[h2] * corr[h2] + rsum[h2];
        }
        #pragma unroll
        for (int nt = 0; nt < 8; nt++) {
            accO[nt][0] *= corr[0]; accO[nt][1] *= corr[0];
            accO[nt][2] *= corr[1]; accO[nt][3] *= corr[1];
        }

        // ---- P fragments (registers, hi/lo split) ----
        uint32_t ph[4][4], pl[4][4];
        #pragma unroll
        for (int js = 0; js < 4; js++) {
            #pragma unroll
            for (int half16 = 0; half16 < 2; half16++) {
                const int nt = 2 * js + half16;
                #pragma unroll
                for (int h2 = 0; h2 < 2; h2++) {
                    const float p0 = sacc[nt][2 * h2], p1 = sacc[nt][2 * h2 + 1];
                    const float h0 = __half2float(__float2half(p0));
                    const float h1 = __half2float(__float2half(p1));
                    ph[js][half16 * 2 + h2] = pack_f16(h0, h1);
                    pl[js][half16 * 2 + h2] = pack_f16(p0 - h0, p1 - h1);
                }
            }
        }

        // ---- O += P V (fp16x2, V via ldmatrix.trans) ----
        const uint32_t vh_base = KV_(buf) + 8192;
        const int vrow = (lane & 7) + (lane & 8);
        const int vcd0 = lane >> 4;
        #pragma unroll
        for (int js = 0; js < 4; js++) {
            #pragma unroll
            for (int ng = 0; ng < 4; ng++) {
                const int rv = js * 16 + vrow;
                const int cd = 2 * ng + vcd0;
                uint32_t vhf[4];
                ldm_x4_t(vhf, vh_base + toff(rv, cd));
                mma_f16(accO[2*ng],   ph[js], vhf[0], vhf[1]);
                mma_f16(accO[2*ng],   pl[js], vhf[0], vhf[1]);
                mma_f16(accO[2*ng+1], ph[js], vhf[2], vhf[3]);
                mma_f16(accO[2*ng+1], pl[js], vhf[2], vhf[3]);
            }
        }
        __syncthreads();
    }

    // ---- write O (fp16 hi/lo) ----
    const float inv0 = 1.0f / l[0], inv1 = 1.0f / l[1];
    #pragma unroll
    for (int nt = 0; nt < 8; nt++) {
        #pragma unroll
        for (int h2 = 0; h2 < 2; h2++) {
            const float inv = h2 ? inv1 : inv0;
            const int gi = q0 + w * 16 + row_in_warp + 8 * h2;
            const size_t o = (rowbase + gi) * DD + col0 + nt * 8 + colpair;
            const float v0 = accO[nt][2 * h2] * inv, v1 = accO[nt][2 * h2 + 1] * inv;
            const float h0 = __half2float(__float2half(v0));
            const float h1 = __half2float(__float2half(v1));
            *(uint32_t*)(Ah + o) = pack_f16(h0, h1);
            *(uint32_t*)(Al + o) = pack_f16(v0 - h0, v1 - h1);
        }
    }
}

// ---------------------------------------------------------------------------
extern "C" void kernel_launch(void* const* d_in, const int* in_sizes, int n_in,
                              void* d_out, int out_size) {
    const float* x  = (const float*)d_in[0];
    const float* Wq = (const float*)d_in[1];
    const float* Wk = (const float*)d_in[2];
    const float* Wv = (const float*)d_in[3];
    const float* Wo = (const float*)d_in[4];
    float* out = (float*)d_out;

    __half *Qh, *Ql, *Kh, *Vh, *xh, *xl, *Ah, *Al, *W;
    cudaGetSymbolAddress((void**)&Qh, g_Qh);
    cudaGetSymbolAddress((void**)&Ql, g_Ql);
    cudaGetSymbolAddress((void**)&Kh, g_Kh);
    cudaGetSymbolAddress((void**)&Vh, g_Vh);
    cudaGetSymbolAddress((void**)&xh, g_xh);
    cudaGetSymbolAddress((void**)&xl, g_xl);
    cudaGetSymbolAddress((void**)&Ah, g_Ah);
    cudaGetSymbolAddress((void**)&Al, g_Al);
    cudaGetSymbolAddress((void**)&W,  g_W);

    static bool attr_done = false;
    if (!attr_done) {
        cudaFuncSetAttribute(gemm_f16x2, cudaFuncAttributeMaxDynamicSharedMemorySize, GEMM_SMEM);
        cudaFuncSetAttribute(attn_tc, cudaFuncAttributeMaxDynamicSharedMemorySize, ATTN_SMEM);
        attr_done = true;
    }

    // input conversions
    split16<<<(NROWS * DD / 4 + 255) / 256, 256>>>(x, xh, xl, NROWS * DD / 4);
    const int wn4 = DD * DD / 4;
    cvt16<<<(wn4 + 255) / 256, 256>>>(Wq, W + 0 * DD * DD, wn4);
    cvt16<<<(wn4 + 255) / 256, 256>>>(Wk, W + 1 * DD * DD, wn4);
    cvt16<<<(wn4 + 255) / 256, 256>>>(Wv, W + 2 * DD * DD, wn4);
    cvt16<<<(wn4 + 255) / 256, 256>>>(Wo, W + 3 * DD * DD, wn4);

    dim3 ggrid(DD / 128, NROWS / 128);   // (8, 32)
    gemm_f16x2<<<ggrid, 256, GEMM_SMEM>>>(xh, xl, W + 0 * DD * DD, nullptr, Qh, Ql);
    gemm_f16x2<<<ggrid, 256, GEMM_SMEM>>>(xh, xl, W + 1 * DD * DD, nullptr, Kh, nullptr);
    gemm_f16x2<<<ggrid, 256, GEMM_SMEM>>>(xh, xl, W + 2 * DD * DD, nullptr, Vh, nullptr);

    attn_tc<<<dim3(TT / 64, HH, BB), 128, ATTN_SMEM>>>(Qh, Ql, Kh, Vh, Ah, Al);

    gemm_f16x2<<<ggrid, 256, GEMM_SMEM>>>(Ah, Al, W + 3 * DD * DD, out, nullptr, nullptr);
}

// round 7
// speedup vs baseline: 5.1128x; 1.5786x over previous
#include <cuda_runtime.h>
#include <cuda_fp16.h>
#include <cstdint>

#define BB 2
#define TT 2048
#define DD 1024
#define HH 16
#define DHH 64
#define NROWS (BB*TT)   // 4096

// Scratch (allocation-free rule: __device__ globals)
__device__ __half g_Qh[NROWS*DD];
__device__ __half g_Ql[NROWS*DD];
__device__ __half g_Kh[NROWS*DD];
__device__ __half g_Vh[NROWS*DD];
__device__ __half g_xh[NROWS*DD];
__device__ __half g_xl[NROWS*DD];
__device__ __half g_Ah[NROWS*DD];
__device__ __half g_Al[NROWS*DD];
__device__ __half g_W[4*DD*DD];

// ---------------------------------------------------------------------------
// helpers (portable PTX: cp.async / ldmatrix / mma.sync)
// ---------------------------------------------------------------------------
__device__ __forceinline__ uint32_t smem_u32(const void* p) {
    uint32_t a;
    asm("{ .reg .u64 t; cvta.to.shared.u64 t, %1; cvt.u32.u64 %0, t; }" : "=r"(a) : "l"(p));
    return a;
}
__device__ __forceinline__ void cp16(uint32_t dst, const void* src) {
    asm volatile("cp.async.cg.shared.global [%0], [%1], 16;" :: "r"(dst), "l"(src));
}
#define CP_COMMIT() asm volatile("cp.async.commit_group;" ::: "memory")
#define CP_WAIT(n)  asm volatile("cp.async.wait_group %0;" :: "n"(n) : "memory")

__device__ __forceinline__ void ldm_x4(uint32_t* r, uint32_t addr) {
    asm volatile("ldmatrix.sync.aligned.m8n8.x4.shared.b16 {%0,%1,%2,%3}, [%4];"
                 : "=r"(r[0]), "=r"(r[1]), "=r"(r[2]), "=r"(r[3]) : "r"(addr));
}
__device__ __forceinline__ void ldm_x4_t(uint32_t* r, uint32_t addr) {
    asm volatile("ldmatrix.sync.aligned.m8n8.x4.trans.shared.b16 {%0,%1,%2,%3}, [%4];"
                 : "=r"(r[0]), "=r"(r[1]), "=r"(r[2]), "=r"(r[3]) : "r"(addr));
}
__device__ __forceinline__ void mma_f16(float* d, const uint32_t* a, uint32_t b0, uint32_t b1) {
    asm volatile(
        "mma.sync.aligned.m16n8k16.row.col.f32.f16.f16.f32 "
        "{%0,%1,%2,%3}, {%4,%5,%6,%7}, {%8,%9}, {%0,%1,%2,%3};"
        : "+f"(d[0]), "+f"(d[1]), "+f"(d[2]), "+f"(d[3])
        : "r"(a[0]), "r"(a[1]), "r"(a[2]), "r"(a[3]), "r"(b0), "r"(b1));
}
__device__ __forceinline__ uint32_t pack_f16(float lo, float hi) {
    __half2 t = __halves2half2(__float2half(lo), __float2half(hi));
    return *(uint32_t*)&t;
}

// ---------------------------------------------------------------------------
// conversions
// ---------------------------------------------------------------------------
__global__ void __launch_bounds__(256) split16(const float* __restrict__ in,
                                               __half* __restrict__ hi,
                                               __half* __restrict__ lo, int n4) {
    int i = blockIdx.x * blockDim.x + threadIdx.x;
    if (i >= n4) return;
    float4 v = ((const float4*)in)[i];
    __align__(8) __half h[4], l[4];
    h[0] = __float2half(v.x); l[0] = __float2half(v.x - __half2float(h[0]));
    h[1] = __float2half(v.y); l[1] = __float2half(v.y - __half2float(h[1]));
    h[2] = __float2half(v.z); l[2] = __float2half(v.z - __half2float(h[2]));
    h[3] = __float2half(v.w); l[3] = __float2half(v.w - __half2float(h[3]));
    ((uint2*)hi)[i] = *(const uint2*)h;
    ((uint2*)lo)[i] = *(const uint2*)l;
}

// all 4 weight matrices -> one fp16 buffer (g_W), one launch
__global__ void __launch_bounds__(256) cvt16x4(const float* __restrict__ w0,
                                               const float* __restrict__ w1,
                                               const float* __restrict__ w2,
                                               const float* __restrict__ w3,
                                               __half* __restrict__ out) {
    const int n4 = DD * DD / 4;
    int i = blockIdx.x * blockDim.x + threadIdx.x;
    if (i >= 4 * n4) return;
    const int m = i / n4;
    const int j = i - m * n4;
    const float* src = (m == 0) ? w0 : (m == 1) ? w1 : (m == 2) ? w2 : w3;
    float4 v = ((const float4*)src)[j];
    __align__(8) __half h[4];
    h[0] = __float2half(v.x); h[1] = __float2half(v.y);
    h[2] = __float2half(v.z); h[3] = __float2half(v.w);
    ((uint2*)out)[i] = *(const uint2*)h;
}

// ---------------------------------------------------------------------------
// GEMM mainloop: C[n,m] = sum_k A[n,k]*B[m,k], fp16x2 (A split hi/lo, B fp16).
// CTA 128x128, BK=32, 512 threads (16 warps, warp tile 32x32).
// 4 smem buffers, 3-deep cp.async pipeline, ONE __syncthreads per stage.
// Stage (24KB): Ah +0, Al +8192, B +16384. Rows 64B, chunk swz c^=(r>>1)&3.
// ---------------------------------------------------------------------------
#define NSTAGE 4
#define STG 24576
#define GEMM_SMEM (NSTAGE * STG)   // 96 KB

__device__ __forceinline__ void gemm_mainloop(
    const __half* __restrict__ Ahg, const __half* __restrict__ Alg,
    const __half* __restrict__ Bg, int n0, int m0,
    uint32_t sbase, float acc[2][4][4]) {
    const int tid  = threadIdx.x;
    const int wid  = tid >> 5;
    const int lane = tid & 31;
    const int warp_m = (wid & 3) * 32;
    const int warp_n = (wid >> 2) * 32;
    const int KT = DD / 32;   // 32

    // loader: thread -> chunk tid of each 8KB tile (row tid>>2, c tid&3)
    const int lrow = tid >> 2;
    const int lc   = tid & 3;
    const uint32_t ld = (uint32_t)(lrow * 64 + ((lc ^ ((lrow >> 1) & 3)) * 16));
    const size_t ga = (size_t)(n0 + lrow) * DD + lc * 8;
    const size_t gb = (size_t)(m0 + lrow) * DD + lc * 8;

    auto load_stage = [&](int s) {
        const int k0 = s * 32;
        const uint32_t stg = sbase + (uint32_t)(s & (NSTAGE - 1)) * STG;
        cp16(stg + 0     + ld, Ahg + ga + k0);
        cp16(stg + 8192  + ld, Alg + ga + k0);
        cp16(stg + 16384 + ld, Bg  + gb + k0);
        CP_COMMIT();
    };

    load_stage(0);
    load_stage(1);
    load_stage(2);

    #pragma unroll
    for (int mt = 0; mt < 2; mt++)
        #pragma unroll
        for (int nt = 0; nt < 4; nt++)
            #pragma unroll
            for (int i = 0; i < 4; i++) acc[mt][nt][i] = 0.0f;

    const int a_r    = (lane & 15);
    const int a_csel = (lane >> 4);
    const int b_g    = (lane >> 3);
    const int b_r    = ((b_g >> 1) << 3) + (lane & 7);
    const int b_csel = (b_g & 1);

    for (int s = 0; s < KT; s++) {
        CP_WAIT(2);        // stage s resident
        __syncthreads();   // also: all warps finished stage s-1 -> buf (s+3)%4 free
        if (s + 3 < KT) load_stage(s + 3);
        else            CP_COMMIT();

        const uint32_t stg = sbase + (uint32_t)(s & (NSTAGE - 1)) * STG;
        #pragma unroll
        for (int kk = 0; kk < 32; kk += 16) {
            const int cbase = kk >> 3;
            uint32_t ah[2][4], al[2][4], bf[2][4];
            #pragma unroll
            for (int mt = 0; mt < 2; mt++) {
                const int r = warp_m + mt * 16 + a_r;
                const int c = (cbase + a_csel) ^ ((r >> 1) & 3);
                const uint32_t ad = (uint32_t)(r * 64 + c * 16);
                ldm_x4(ah[mt], stg + 0    + ad);
                ldm_x4(al[mt], stg + 8192 + ad);
            }
            #pragma unroll
            for (int ng = 0; ng < 2; ng++) {
                const int r = warp_n + ng * 16 + b_r;
                const int c = (cbase + b_csel) ^ ((r >> 1) & 3);
                ldm_x4(bf[ng], stg + 16384 + (uint32_t)(r * 64 + c * 16));
            }
            #pragma unroll
            for (int mt = 0; mt < 2; mt++)
                #pragma unroll
                for (int nt = 0; nt < 4; nt++) {
                    const uint32_t b0 = bf[nt >> 1][(nt & 1) * 2];
                    const uint32_t b1 = bf[nt >> 1][(nt & 1) * 2 + 1];
                    mma_f16(acc[mt][nt], ah[mt], b0, b1);
                    mma_f16(acc[mt][nt], al[mt], b0, b1);
                }
        }
    }
}

// fused Q/K/V projection: grid (24, 32); blockIdx.x>>3 selects Wq/Wk/Wv.
__global__ void __launch_bounds__(512, 1) gemm_qkv(
    const __half* __restrict__ xh, const __half* __restrict__ xl,
    const __half* __restrict__ W,
    __half* __restrict__ Qh, __half* __restrict__ Ql,
    __half* __restrict__ Kh, __half* __restrict__ Vh) {
    extern __shared__ __align__(128) char smem[];
    const int wsel = blockIdx.x >> 3;
    const int m0 = (blockIdx.x & 7) * 128;
    const int n0 = blockIdx.y * 128;

    float acc[2][4][4];
    gemm_mainloop(xh, xl, W + (size_t)wsel * DD * DD, n0, m0, smem_u32(smem), acc);

    const int wid  = threadIdx.x >> 5;
    const int lane = threadIdx.x & 31;
    const int warp_m = (wid & 3) * 32;
    const int warp_n = (wid >> 2) * 32;

    #pragma unroll
    for (int mt = 0; mt < 2; mt++)
        #pragma unroll
        for (int nt = 0; nt < 4; nt++) {
            const int r   = n0 + warp_m + mt * 16 + (lane >> 2);
            const int col = m0 + warp_n + nt * 8 + (lane & 3) * 2;
            #pragma unroll
            for (int h2 = 0; h2 < 2; h2++) {
                const float v0 = acc[mt][nt][2 * h2], v1 = acc[mt][nt][2 * h2 + 1];
                const size_t o = (size_t)(r + 8 * h2) * DD + col;
                if (wsel == 0) {
                    const float h0 = __half2float(__float2half(v0));
                    const float h1 = __half2float(__float2half(v1));
                    *(uint32_t*)(Qh + o) = pack_f16(h0, h1);
                    *(uint32_t*)(Ql + o) = pack_f16(v0 - h0, v1 - h1);
                } else if (wsel == 1) {
                    *(uint32_t*)(Kh + o) = pack_f16(v0, v1);
                } else {
                    *(uint32_t*)(Vh + o) = pack_f16(v0, v1);
                }
            }
        }
}

// output projection: grid (8, 32); fp32 out.
__global__ void __launch_bounds__(512, 1) gemm_out(
    const __half* __restrict__ Ah, const __half* __restrict__ Al,
    const __half* __restrict__ W, float* __restrict__ out) {
    extern __shared__ __align__(128) char smem[];
    const int m0 = blockIdx.x * 128;
    const int n0 = blockIdx.y * 128;

    float acc[2][4][4];
    gemm_mainloop(Ah, Al, W, n0, m0, smem_u32(smem), acc);

    const int wid  = threadIdx.x >> 5;
    const int lane = threadIdx.x & 31;
    const int warp_m = (wid & 3) * 32;
    const int warp_n = (wid >> 2) * 32;

    #pragma unroll
    for (int mt = 0; mt < 2; mt++)
        #pragma unroll
        for (int nt = 0; nt < 4; nt++) {
            const int r   = n0 + warp_m + mt * 16 + (lane >> 2);
            const int col = m0 + warp_n + nt * 8 + (lane & 3) * 2;
            float2 v0 = {acc[mt][nt][0], acc[mt][nt][1]};
            float2 v1 = {acc[mt][nt][2], acc[mt][nt][3]};
            *(float2*)(out + (size_t)r * DD + col)       = v0;
            *(float2*)(out + (size_t)(r + 8) * DD + col) = v1;
        }
}

// ---------------------------------------------------------------------------
// Tensor-core sliding-window flash attention (fp16x2: Q & P split, K/V plain).
// CTA: 64 queries x (b,h); 4 warps, warp = 16 queries x 64 keys.
// ---------------------------------------------------------------------------
#define ATTN_SMEM (16384 + 2*16384)

__global__ void __launch_bounds__(128, 2) attn_tc(
    const __half* __restrict__ Qh, const __half* __restrict__ Ql,
    const __half* __restrict__ Kh, const __half* __restrict__ Vh,
    __half* __restrict__ Ah, __half* __restrict__ Al) {
    extern __shared__ __align__(128) char smem[];
    const uint32_t sb = smem_u32(smem);
    const int tid = threadIdx.x;
    const int lane = tid & 31;
    const int w = tid >> 5;
    const int q0 = blockIdx.x * 64;
    const int h = blockIdx.y;
    const int b = blockIdx.z;
    const size_t rowbase = (size_t)b * TT;
    const int col0 = h * DHH;

    const uint32_t QH_ = sb, QL_ = sb + 8192;
    auto KV_ = [&](int buf) { return sb + 16384 + (uint32_t)buf * 16384; };

    auto toff = [](int r, int cd) { return (uint32_t)(r * 128 + ((cd ^ (r & 7)) << 4)); };

    const int lr = tid >> 1;
    const int lc0 = (tid & 1) * 4;
    auto load_q = [&]() {
        const size_t g = (rowbase + q0 + lr) * DD + col0;
        #pragma unroll
        for (int c = 0; c < 4; c++) {
            const int cd = lc0 + c;
            cp16(QH_ + toff(lr, cd), Qh + g + cd * 8);
            cp16(QL_ + toff(lr, cd), Ql + g + cd * 8);
        }
    };
    auto load_kv = [&](int c, int buf) {
        const size_t g = (rowbase + c * 64 + lr) * DD + col0;
        const uint32_t base = KV_(buf);
        #pragma unroll
        for (int cc = 0; cc < 4; cc++) {
            const int cd = lc0 + cc;
            const uint32_t d = toff(lr, cd);
            cp16(base + 0    + d, Kh + g + cd * 8);
            cp16(base + 8192 + d, Vh + g + cd * 8);
        }
    };

    const int c_lo = (q0 >= 128) ? ((q0 - 128) >> 6) : 0;
    const int c_hi = q0 >> 6;

    load_q();
    load_kv(c_lo, c_lo & 1);
    CP_COMMIT();

    float m[2] = {-1e30f, -1e30f}, l[2] = {0.0f, 0.0f};
    float accO[8][4];
    #pragma unroll
    for (int nt = 0; nt < 8; nt++)
        #pragma unroll
        for (int i = 0; i < 4; i++) accO[nt][i] = 0.0f;

    uint32_t qhf[4][4], qlf[4][4];
    bool qloaded = false;

    const int row_in_warp = lane >> 2;
    const int colpair = (lane & 3) * 2;

    for (int c = c_lo; c <= c_hi; c++) {
        const int buf = c & 1;
        if (c < c_hi) { load_kv(c + 1, (c + 1) & 1); CP_COMMIT(); CP_WAIT(1); }
        else          { CP_WAIT(0); }
        __syncthreads();

        if (!qloaded) {
            qloaded = true;
            #pragma unroll
            for (int ks = 0; ks < 4; ks++) {
                const int r = w * 16 + (lane & 15);
                const int cd = 2 * ks + (lane >> 4);
                ldm_x4(qhf[ks], QH_ + toff(r, cd));
                ldm_x4(qlf[ks], QL_ + toff(r, cd));
            }
        }

        // ---- S = Q K^T (fp16x2) ----
        float sacc[8][4];
        #pragma unroll
        for (int nt = 0; nt < 8; nt++)
            #pragma unroll
            for (int i = 0; i < 4; i++) sacc[nt][i] = 0.0f;

        const uint32_t kh_base = KV_(buf);
        const int krow = (lane & 7) + ((lane & 16) >> 1);
        const int kcd0 = (lane >> 3) & 1;
        #pragma unroll
        for (int ks = 0; ks < 4; ks++) {
            #pragma unroll
            for (int ng = 0; ng < 4; ng++) {
                const int rn = ng * 16 + krow;
                const int cd = 2 * ks + kcd0;
                uint32_t bh[4];
                ldm_x4(bh, kh_base + toff(rn, cd));
                mma_f16(sacc[2*ng],   qhf[ks], bh[0], bh[1]);
                mma_f16(sacc[2*ng],   qlf[ks], bh[0], bh[1]);
                mma_f16(sacc[2*ng+1], qhf[ks], bh[2], bh[3]);
                mma_f16(sacc[2*ng+1], qlf[ks], bh[2], bh[3]);
            }
        }

        // ---- mask + scale + online softmax ----
        const int kbase = c * 64;
        float rmax[2] = {-1e30f, -1e30f};
        #pragma unroll
        for (int nt = 0; nt < 8; nt++)
            #pragma unroll
            for (int e2 = 0; e2 < 4; e2++) {
                const int h2 = e2 >> 1;
                const int key = kbase + nt * 8 + colpair + (e2 & 1);
                const int iq  = q0 + w * 16 + row_in_warp + 8 * h2;
                float s = sacc[nt][e2] * 0.125f;
                s = (key <= iq && key + 128 >= iq) ? s : -1e30f;
                sacc[nt][e2] = s;
                rmax[h2] = fmaxf(rmax[h2], s);
            }
        #pragma unroll
        for (int h2 = 0; h2 < 2; h2++) {
            rmax[h2] = fmaxf(rmax[h2], __shfl_xor_sync(0xffffffffu, rmax[h2], 1));
            rmax[h2] = fmaxf(rmax[h2], __shfl_xor_sync(0xffffffffu, rmax[h2], 2));
        }
        float corr[2], rsum[2] = {0.0f, 0.0f};
        #pragma unroll
        for (int h2 = 0; h2 < 2; h2++) {
            const float newm = fmaxf(m[h2], rmax[h2]);
            corr[h2] = __expf(m[h2] - newm);
            m[h2] = newm;
        }
        #pragma unroll
        for (int nt = 0; nt < 8; nt++)
            #pragma unroll
            for (int e2 = 0; e2 < 4; e2++) {
                const int h2 = e2 >> 1;
                const float p = __expf(sacc[nt][e2] - m[h2]);
                sacc[nt][e2] = p;
                rsum[h2] += p;
            }
        #pragma unroll
        for (int h2 = 0; h2 < 2; h2++) {
            rsum[h2] += __shfl_xor_sync(0xffffffffu, rsum[h2], 1);
            rsum[h2] += __shfl_xor_sync(0xffffffffu, rsum[h2], 2);
            l[h2] = l[h2] * corr[h2] + rsum[h2];
        }
        #pragma unroll
        for (int nt = 0; nt < 8; nt++) {
            accO[nt][0] *= corr[0]; accO[nt][1] *= corr[0];
            accO[nt][2] *= corr[1]; accO[nt][3] *= corr[1];
        }

        // ---- P fragments (registers, hi/lo split) ----
        uint32_t ph[4][4], pl[4][4];
        #pragma unroll
        for (int js = 0; js < 4; js++) {
            #pragma unroll
            for (int half16 = 0; half16 < 2; half16++) {
                const int nt = 2 * js + half16;
                #pragma unroll
                for (int h2 = 0; h2 < 2; h2++) {
                    const float p0 = sacc[nt][2 * h2], p1 = sacc[nt][2 * h2 + 1];
                    const float h0 = __half2float(__float2half(p0));
                    const float h1 = __half2float(__float2half(p1));
                    ph[js][half16 * 2 + h2] = pack_f16(h0, h1);
                    pl[js][half16 * 2 + h2] = pack_f16(p0 - h0, p1 - h1);
                }
            }
        }

        // ---- O += P V (fp16x2, V via ldmatrix.trans) ----
        const uint32_t vh_base = KV_(buf) + 8192;
        const int vrow = (lane & 7) + (lane & 8);
        const int vcd0 = lane >> 4;
        #pragma unroll
        for (int js = 0; js < 4; js++) {
            #pragma unroll
            for (int ng = 0; ng < 4; ng++) {
                const int rv = js * 16 + vrow;
                const int cd = 2 * ng + vcd0;
                uint32_t vhf[4];
                ldm_x4_t(vhf, vh_base + toff(rv, cd));
                mma_f16(accO[2*ng],   ph[js], vhf[0], vhf[1]);
                mma_f16(accO[2*ng],   pl[js], vhf[0], vhf[1]);
                mma_f16(accO[2*ng+1], ph[js], vhf[2], vhf[3]);
                mma_f16(accO[2*ng+1], pl[js], vhf[2], vhf[3]);
            }
        }
        __syncthreads();
    }

    // ---- write O (fp16 hi/lo) ----
    const float inv0 = 1.0f / l[0], inv1 = 1.0f / l[1];
    #pragma unroll
    for (int nt = 0; nt < 8; nt++) {
        #pragma unroll
        for (int h2 = 0; h2 < 2; h2++) {
            const float inv = h2 ? inv1 : inv0;
            const int gi = q0 + w * 16 + row_in_warp + 8 * h2;
            const size_t o = (rowbase + gi) * DD + col0 + nt * 8 + colpair;
            const float v0 = accO[nt][2 * h2] * inv, v1 = accO[nt][2 * h2 + 1] * inv;
            const float h0 = __half2float(__float2half(v0));
            const float h1 = __half2float(__float2half(v1));
            *(uint32_t*)(Ah + o) = pack_f16(h0, h1);
            *(uint32_t*)(Al + o) = pack_f16(v0 - h0, v1 - h1);
        }
    }
}

// ---------------------------------------------------------------------------
extern "C" void kernel_launch(void* const* d_in, const int* in_sizes, int n_in,
                              void* d_out, int out_size) {
    const float* x  = (const float*)d_in[0];
    const float* Wq = (const float*)d_in[1];
    const float* Wk = (const float*)d_in[2];
    const float* Wv = (const float*)d_in[3];
    const float* Wo = (const float*)d_in[4];
    float* out = (float*)d_out;

    __half *Qh, *Ql, *Kh, *Vh, *xh, *xl, *Ah, *Al, *W;
    cudaGetSymbolAddress((void**)&Qh, g_Qh);
    cudaGetSymbolAddress((void**)&Ql, g_Ql);
    cudaGetSymbolAddress((void**)&Kh, g_Kh);
    cudaGetSymbolAddress((void**)&Vh, g_Vh);
    cudaGetSymbolAddress((void**)&xh, g_xh);
    cudaGetSymbolAddress((void**)&xl, g_xl);
    cudaGetSymbolAddress((void**)&Ah, g_Ah);
    cudaGetSymbolAddress((void**)&Al, g_Al);
    cudaGetSymbolAddress((void**)&W,  g_W);

    static bool attr_done = false;
    if (!attr_done) {
        cudaFuncSetAttribute(gemm_qkv, cudaFuncAttributeMaxDynamicSharedMemorySize, GEMM_SMEM);
        cudaFuncSetAttribute(gemm_out, cudaFuncAttributeMaxDynamicSharedMemorySize, GEMM_SMEM);
        cudaFuncSetAttribute(attn_tc, cudaFuncAttributeMaxDynamicSharedMemorySize, ATTN_SMEM);
        attr_done = true;
    }

    split16<<<(NROWS * DD / 4 + 255) / 256, 256>>>(x, xh, xl, NROWS * DD / 4);
    cvt16x4<<<(DD * DD + 255) / 256, 256>>>(Wq, Wk, Wv, Wo, W);

    gemm_qkv<<<dim3(24, 32), 512, GEMM_SMEM>>>(xh, xl, W, Qh, Ql, Kh, Vh);

    attn_tc<<<dim3(TT / 64, HH, BB), 128, ATTN_SMEM>>>(Qh, Ql, Kh, Vh, Ah, Al);

    gemm_out<<<dim3(8, 32), 512, GEMM_SMEM>>>(Ah, Al, W + 3 * (size_t)DD * DD, out);
}

// round 8
// speedup vs baseline: 8.3965x; 1.6423x over previous
#include <cuda_runtime.h>
#include <cuda_fp16.h>
#include <cstdint>

#define BB 2
#define TT 2048
#define DD 1024
#define HH 16
#define DHH 64
#define NROWS (BB*TT)   // 4096

// Scratch (allocation-free rule: __device__ globals)
__device__ __half g_Qh[NROWS*DD];
__device__ __half g_Ql[NROWS*DD];
__device__ __half g_Kh[NROWS*DD];
__device__ __half g_Vh[NROWS*DD];
__device__ __half g_xh[NROWS*DD];
__device__ __half g_Ah[NROWS*DD];
__device__ __half g_W[4*DD*DD];

// ---------------------------------------------------------------------------
// helpers (portable PTX: cp.async / ldmatrix / mma.sync)
// ---------------------------------------------------------------------------
__device__ __forceinline__ uint32_t smem_u32(const void* p) {
    uint32_t a;
    asm("{ .reg .u64 t; cvta.to.shared.u64 t, %1; cvt.u32.u64 %0, t; }" : "=r"(a) : "l"(p));
    return a;
}
__device__ __forceinline__ void cp16(uint32_t dst, const void* src) {
    asm volatile("cp.async.cg.shared.global [%0], [%1], 16;" :: "r"(dst), "l"(src));
}
#define CP_COMMIT() asm volatile("cp.async.commit_group;" ::: "memory")
#define CP_WAIT(n)  asm volatile("cp.async.wait_group %0;" :: "n"(n) : "memory")

__device__ __forceinline__ void ldm_x4(uint32_t* r, uint32_t addr) {
    asm volatile("ldmatrix.sync.aligned.m8n8.x4.shared.b16 {%0,%1,%2,%3}, [%4];"
                 : "=r"(r[0]), "=r"(r[1]), "=r"(r[2]), "=r"(r[3]) : "r"(addr));
}
__device__ __forceinline__ void ldm_x4_t(uint32_t* r, uint32_t addr) {
    asm volatile("ldmatrix.sync.aligned.m8n8.x4.trans.shared.b16 {%0,%1,%2,%3}, [%4];"
                 : "=r"(r[0]), "=r"(r[1]), "=r"(r[2]), "=r"(r[3]) : "r"(addr));
}
__device__ __forceinline__ void mma_f16(float* d, const uint32_t* a, uint32_t b0, uint32_t b1) {
    asm volatile(
        "mma.sync.aligned.m16n8k16.row.col.f32.f16.f16.f32 "
        "{%0,%1,%2,%3}, {%4,%5,%6,%7}, {%8,%9}, {%0,%1,%2,%3};"
        : "+f"(d[0]), "+f"(d[1]), "+f"(d[2]), "+f"(d[3])
        : "r"(a[0]), "r"(a[1]), "r"(a[2]), "r"(a[3]), "r"(b0), "r"(b1));
}
__device__ __forceinline__ uint32_t pack_f16(float lo, float hi) {
    __half2 t = __halves2half2(__float2half(lo), __float2half(hi));
    return *(uint32_t*)&t;
}

// ---------------------------------------------------------------------------
// one-shot conversion: x and all 4 weights -> fp16
// index space: [0, 1M) -> x (1M float4), [1M, 2M) -> weights (4 x 256K float4)
// ---------------------------------------------------------------------------
__global__ void __launch_bounds__(256) cvt_all(const float* __restrict__ x,
                                               const float* __restrict__ w0,
                                               const float* __restrict__ w1,
                                               const float* __restrict__ w2,
                                               const float* __restrict__ w3,
                                               __half* __restrict__ xh,
                                               __half* __restrict__ W) {
    const int XN4 = NROWS * DD / 4;        // 1M
    const int WN4 = DD * DD / 4;           // 256K
    int i = blockIdx.x * blockDim.x + threadIdx.x;
    if (i >= XN4 + 4 * WN4) return;
    const float* src;
    uint2* dst;
    int j;
    if (i < XN4) {
        src = x; dst = (uint2*)xh; j = i;
    } else {
        const int t = i - XN4;
        const int m = t / WN4;
        j = t - m * WN4;
        src = (m == 0) ? w0 : (m == 1) ? w1 : (m == 2) ? w2 : w3;
        dst = (uint2*)W + (size_t)m * WN4;
    }
    float4 v = ((const float4*)src)[j];
    __align__(8) __half h[4];
    h[0] = __float2half(v.x); h[1] = __float2half(v.y);
    h[2] = __float2half(v.z); h[3] = __float2half(v.w);
    dst[j] = *(const uint2*)h;
}

// ---------------------------------------------------------------------------
// GEMM mainloop: C[n,m] = sum_k A[n,k]*B[m,k], single fp16 operands.
// CTA 128x128, BK=32, 512 threads (16 warps, warp tile 32x32).
// 8 smem buffers (16KB each: A +0, B +8192), depth-6 cp.async pipeline,
// one __syncthreads per stage. Rows 64B, chunk swz c^=(r>>1)&3.
// ---------------------------------------------------------------------------
#define NSTAGE 8
#define STG 16384
#define GEMM_SMEM (NSTAGE * STG)   // 128 KB

__device__ __forceinline__ void gemm_mainloop(
    const __half* __restrict__ Ag, const __half* __restrict__ Bg,
    int n0, int m0, uint32_t sbase, float acc[2][4][4]) {
    const int tid  = threadIdx.x;
    const int wid  = tid >> 5;
    const int lane = tid & 31;
    const int warp_m = (wid & 3) * 32;
    const int warp_n = (wid >> 2) * 32;
    const int KT = DD / 32;   // 32

    const int lrow = tid >> 2;
    const int lc   = tid & 3;
    const uint32_t ld = (uint32_t)(lrow * 64 + ((lc ^ ((lrow >> 1) & 3)) * 16));
    const size_t ga = (size_t)(n0 + lrow) * DD + lc * 8;
    const size_t gb = (size_t)(m0 + lrow) * DD + lc * 8;

    auto load_stage = [&](int s) {
        const int k0 = s * 32;
        const uint32_t stg = sbase + (uint32_t)(s & (NSTAGE - 1)) * STG;
        cp16(stg + 0    + ld, Ag + ga + k0);
        cp16(stg + 8192 + ld, Bg + gb + k0);
        CP_COMMIT();
    };

    #pragma unroll
    for (int s = 0; s < 6; s++) load_stage(s);

    #pragma unroll
    for (int mt = 0; mt < 2; mt++)
        #pragma unroll
        for (int nt = 0; nt < 4; nt++)
            #pragma unroll
            for (int i = 0; i < 4; i++) acc[mt][nt][i] = 0.0f;

    const int a_r    = (lane & 15);
    const int a_csel = (lane >> 4);
    const int b_g    = (lane >> 3);
    const int b_r    = ((b_g >> 1) << 3) + (lane & 7);
    const int b_csel = (b_g & 1);

    for (int s = 0; s < KT; s++) {
        CP_WAIT(5);        // stage s resident
        __syncthreads();   // all warps past stage s-1 -> buf (s+6)&7 free
        if (s + 6 < KT) load_stage(s + 6);
        else            CP_COMMIT();

        const uint32_t stg = sbase + (uint32_t)(s & (NSTAGE - 1)) * STG;
        #pragma unroll
        for (int kk = 0; kk < 32; kk += 16) {
            const int cbase = kk >> 3;
            uint32_t af[2][4], bf[2][4];
            #pragma unroll
            for (int mt = 0; mt < 2; mt++) {
                const int r = warp_m + mt * 16 + a_r;
                const int c = (cbase + a_csel) ^ ((r >> 1) & 3);
                ldm_x4(af[mt], stg + 0 + (uint32_t)(r * 64 + c * 16));
            }
            #pragma unroll
            for (int ng = 0; ng < 2; ng++) {
                const int r = warp_n + ng * 16 + b_r;
                const int c = (cbase + b_csel) ^ ((r >> 1) & 3);
                ldm_x4(bf[ng], stg + 8192 + (uint32_t)(r * 64 + c * 16));
            }
            #pragma unroll
            for (int mt = 0; mt < 2; mt++)
                #pragma unroll
                for (int nt = 0; nt < 4; nt++) {
                    const uint32_t b0 = bf[nt >> 1][(nt & 1) * 2];
                    const uint32_t b1 = bf[nt >> 1][(nt & 1) * 2 + 1];
                    mma_f16(acc[mt][nt], af[mt], b0, b1);
                }
        }
    }
}

// fused Q/K/V projection: grid (24, 32); blockIdx.x>>3 selects Wq/Wk/Wv.
__global__ void __launch_bounds__(512, 1) gemm_qkv(
    const __half* __restrict__ xh, const __half* __restrict__ W,
    __half* __restrict__ Qh, __half* __restrict__ Ql,
    __half* __restrict__ Kh, __half* __restrict__ Vh) {
    extern __shared__ __align__(128) char smem[];
    const int wsel = blockIdx.x >> 3;
    const int m0 = (blockIdx.x & 7) * 128;
    const int n0 = blockIdx.y * 128;

    float acc[2][4][4];
    gemm_mainloop(xh, W + (size_t)wsel * DD * DD, n0, m0, smem_u32(smem), acc);

    const int wid  = threadIdx.x >> 5;
    const int lane = threadIdx.x & 31;
    const int warp_m = (wid & 3) * 32;
    const int warp_n = (wid >> 2) * 32;

    #pragma unroll
    for (int mt = 0; mt < 2; mt++)
        #pragma unroll
        for (int nt = 0; nt < 4; nt++) {
            const int r   = n0 + warp_m + mt * 16 + (lane >> 2);
            const int col = m0 + warp_n + nt * 8 + (lane & 3) * 2;
            #pragma unroll
            for (int h2 = 0; h2 < 2; h2++) {
                const float v0 = acc[mt][nt][2 * h2], v1 = acc[mt][nt][2 * h2 + 1];
                const size_t o = (size_t)(r + 8 * h2) * DD + col;
                if (wsel == 0) {
                    const float h0 = __half2float(__float2half(v0));
                    const float h1 = __half2float(__float2half(v1));
                    *(uint32_t*)(Qh + o) = pack_f16(h0, h1);
                    *(uint32_t*)(Ql + o) = pack_f16(v0 - h0, v1 - h1);
                } else if (wsel == 1) {
                    *(uint32_t*)(Kh + o) = pack_f16(v0, v1);
                } else {
                    *(uint32_t*)(Vh + o) = pack_f16(v0, v1);
                }
            }
        }
}

// output projection: grid (8, 32); fp32 out.
__global__ void __launch_bounds__(512, 1) gemm_out(
    const __half* __restrict__ Ah, const __half* __restrict__ W,
    float* __restrict__ out) {
    extern __shared__ __align__(128) char smem[];
    const int m0 = blockIdx.x * 128;
    const int n0 = blockIdx.y * 128;

    float acc[2][4][4];
    gemm_mainloop(Ah, W, n0, m0, smem_u32(smem), acc);

    const int wid  = threadIdx.x >> 5;
    const int lane = threadIdx.x & 31;
    const int warp_m = (wid & 3) * 32;
    const int warp_n = (wid >> 2) * 32;

    #pragma unroll
    for (int mt = 0; mt < 2; mt++)
        #pragma unroll
        for (int nt = 0; nt < 4; nt++) {
            const int r   = n0 + warp_m + mt * 16 + (lane >> 2);
            const int col = m0 + warp_n + nt * 8 + (lane & 3) * 2;
            float2 v0 = {acc[mt][nt][0], acc[mt][nt][1]};
            float2 v1 = {acc[mt][nt][2], acc[mt][nt][3]};
            *(float2*)(out + (size_t)r * DD + col)       = v0;
            *(float2*)(out + (size_t)(r + 8) * DD + col) = v1;
        }
}

// ---------------------------------------------------------------------------
// Tensor-core sliding-window flash attention (fp16x2: Q & P split, K/V plain).
// CTA: 64 queries x (b,h); 4 warps, warp = 16 queries x 64 keys.
// Output: single fp16 (Ah).
// ---------------------------------------------------------------------------
#define ATTN_SMEM (16384 + 2*16384)

__global__ void __launch_bounds__(128, 2) attn_tc(
    const __half* __restrict__ Qh, const __half* __restrict__ Ql,
    const __half* __restrict__ Kh, const __half* __restrict__ Vh,
    __half* __restrict__ Ah) {
    extern __shared__ __align__(128) char smem[];
    const uint32_t sb = smem_u32(smem);
    const int tid = threadIdx.x;
    const int lane = tid & 31;
    const int w = tid >> 5;
    const int q0 = blockIdx.x * 64;
    const int h = blockIdx.y;
    const int b = blockIdx.z;
    const size_t rowbase = (size_t)b * TT;
    const int col0 = h * DHH;

    const uint32_t QH_ = sb, QL_ = sb + 8192;
    auto KV_ = [&](int buf) { return sb + 16384 + (uint32_t)buf * 16384; };

    auto toff = [](int r, int cd) { return (uint32_t)(r * 128 + ((cd ^ (r & 7)) << 4)); };

    const int lr = tid >> 1;
    const int lc0 = (tid & 1) * 4;
    auto load_q = [&]() {
        const size_t g = (rowbase + q0 + lr) * DD + col0;
        #pragma unroll
        for (int c = 0; c < 4; c++) {
            const int cd = lc0 + c;
            cp16(QH_ + toff(lr, cd), Qh + g + cd * 8);
            cp16(QL_ + toff(lr, cd), Ql + g + cd * 8);
        }
    };
    auto load_kv = [&](int c, int buf) {
        const size_t g = (rowbase + c * 64 + lr) * DD + col0;
        const uint32_t base = KV_(buf);
        #pragma unroll
        for (int cc = 0; cc < 4; cc++) {
            const int cd = lc0 + cc;
            const uint32_t d = toff(lr, cd);
            cp16(base + 0    + d, Kh + g + cd * 8);
            cp16(base + 8192 + d, Vh + g + cd * 8);
        }
    };

    const int c_lo = (q0 >= 128) ? ((q0 - 128) >> 6) : 0;
    const int c_hi = q0 >> 6;

    load_q();
    load_kv(c_lo, c_lo & 1);
    CP_COMMIT();

    float m[2] = {-1e30f, -1e30f}, l[2] = {0.0f, 0.0f};
    float accO[8][4];
    #pragma unroll
    for (int nt = 0; nt < 8; nt++)
        #pragma unroll
        for (int i = 0; i < 4; i++) accO[nt][i] = 0.0f;

    uint32_t qhf[4][4], qlf[4][4];
    bool qloaded = false;

    const int row_in_warp = lane >> 2;
    const int colpair = (lane & 3) * 2;

    for (int c = c_lo; c <= c_hi; c++) {
        const int buf = c & 1;
        if (c < c_hi) { load_kv(c + 1, (c + 1) & 1); CP_COMMIT(); CP_WAIT(1); }
        else          { CP_WAIT(0); }
        __syncthreads();

        if (!qloaded) {
            qloaded = true;
            #pragma unroll
            for (int ks = 0; ks < 4; ks++) {
                const int r = w * 16 + (lane & 15);
                const int cd = 2 * ks + (lane >> 4);
                ldm_x4(qhf[ks], QH_ + toff(r, cd));
                ldm_x4(qlf[ks], QL_ + toff(r, cd));
            }
        }

        // ---- S = Q K^T (fp16x2) ----
        float sacc[8][4];
        #pragma unroll
        for (int nt = 0; nt < 8; nt++)
            #pragma unroll
            for (int i = 0; i < 4; i++) sacc[nt][i] = 0.0f;

        const uint32_t kh_base = KV_(buf);
        const int krow = (lane & 7) + ((lane & 16) >> 1);
        const int kcd0 = (lane >> 3) & 1;
        #pragma unroll
        for (int ks = 0; ks < 4; ks++) {
            #pragma unroll
            for (int ng = 0; ng < 4; ng++) {
                const int rn = ng * 16 + krow;
                const int cd = 2 * ks + kcd0;
                uint32_t bh[4];
                ldm_x4(bh, kh_base + toff(rn, cd));
                mma_f16(sacc[2*ng],   qhf[ks], bh[0], bh[1]);
                mma_f16(sacc[2*ng],   qlf[ks], bh[0], bh[1]);
                mma_f16(sacc[2*ng+1], qhf[ks], bh[2], bh[3]);
                mma_f16(sacc[2*ng+1], qlf[ks], bh[2], bh[3]);
            }
        }

        // ---- mask + scale + online softmax ----
        const int kbase = c * 64;
        float rmax[2] = {-1e30f, -1e30f};
        #pragma unroll
        for (int nt = 0; nt < 8; nt++)
            #pragma unroll
            for (int e2 = 0; e2 < 4; e2++) {
                const int h2 = e2 >> 1;
                const int key = kbase + nt * 8 + colpair + (e2 & 1);
                const int iq  = q0 + w * 16 + row_in_warp + 8 * h2;
                float s = sacc[nt][e2] * 0.125f;
                s = (key <= iq && key + 128 >= iq) ? s : -1e30f;
                sacc[nt][e2] = s;
                rmax[h2] = fmaxf(rmax[h2], s);
            }
        #pragma unroll
        for (int h2 = 0; h2 < 2; h2++) {
            rmax[h2] = fmaxf(rmax[h2], __shfl_xor_sync(0xffffffffu, rmax[h2], 1));
            rmax[h2] = fmaxf(rmax[h2], __shfl_xor_sync(0xffffffffu, rmax[h2], 2));
        }
        float corr[2], rsum[2] = {0.0f, 0.0f};
        #pragma unroll
        for (int h2 = 0; h2 < 2; h2++) {
            const float newm = fmaxf(m[h2], rmax[h2]);
            corr[h2] = __expf(m[h2] - newm);
            m[h2] = newm;
        }
        #pragma unroll
        for (int nt = 0; nt < 8; nt++)
            #pragma unroll
            for (int e2 = 0; e2 < 4; e2++) {
                const int h2 = e2 >> 1;
                const float p = __expf(sacc[nt][e2] - m[h2]);
                sacc[nt][e2] = p;
                rsum[h2] += p;
            }
        #pragma unroll
        for (int h2 = 0; h2 < 2; h2++) {
            rsum[h2] += __shfl_xor_sync(0xffffffffu, rsum[h2], 1);
            rsum[h2] += __shfl_xor_sync(0xffffffffu, rsum[h2], 2);
            l[h2] = l[h2] * corr[h2] + rsum[h2];
        }
        #pragma unroll
        for (int nt = 0; nt < 8; nt++) {
            accO[nt][0] *= corr[0]; accO[nt][1] *= corr[0];
            accO[nt][2] *= corr[1]; accO[nt][3] *= corr[1];
        }

        // ---- P fragments (registers, hi/lo split) ----
        uint32_t ph[4][4], pl[4][4];
        #pragma unroll
        for (int js = 0; js < 4; js++) {
            #pragma unroll
            for (int half16 = 0; half16 < 2; half16++) {
                const int nt = 2 * js + half16;
                #pragma unroll
                for (int h2 = 0; h2 < 2; h2++) {
                    const float p0 = sacc[nt][2 * h2], p1 = sacc[nt][2 * h2 + 1];
                    const float h0 = __half2float(__float2half(p0));
                    const float h1 = __half2float(__float2half(p1));
                    ph[js][half16 * 2 + h2] = pack_f16(h0, h1);
                    pl[js][half16 * 2 + h2] = pack_f16(p0 - h0, p1 - h1);
                }
            }
        }

        // ---- O += P V (fp16x2, V via ldmatrix.trans) ----
        const uint32_t vh_base = KV_(buf) + 8192;
        const int vrow = (lane & 7) + (lane & 8);
        const int vcd0 = lane >> 4;
        #pragma unroll
        for (int js = 0; js < 4; js++) {
            #pragma unroll
            for (int ng = 0; ng < 4; ng++) {
                const int rv = js * 16 + vrow;
                const int cd = 2 * ng + vcd0;
                uint32_t vhf[4];
                ldm_x4_t(vhf, vh_base + toff(rv, cd));
                mma_f16(accO[2*ng],   ph[js], vhf[0], vhf[1]);
                mma_f16(accO[2*ng],   pl[js], vhf[0], vhf[1]);
                mma_f16(accO[2*ng+1], ph[js], vhf[2], vhf[3]);
                mma_f16(accO[2*ng+1], pl[js], vhf[2], vhf[3]);
            }
        }
        __syncthreads();
    }

    // ---- write O (single fp16) ----
    const float inv0 = 1.0f / l[0], inv1 = 1.0f / l[1];
    #pragma unroll
    for (int nt = 0; nt < 8; nt++) {
        #pragma unroll
        for (int h2 = 0; h2 < 2; h2++) {
            const float inv = h2 ? inv1 : inv0;
            const int gi = q0 + w * 16 + row_in_warp + 8 * h2;
            const size_t o = (rowbase + gi) * DD + col0 + nt * 8 + colpair;
            *(uint32_t*)(Ah + o) = pack_f16(accO[nt][2 * h2] * inv,
                                            accO[nt][2 * h2 + 1] * inv);
        }
    }
}

// ---------------------------------------------------------------------------
extern "C" void kernel_launch(void* const* d_in, const int* in_sizes, int n_in,
                              void* d_out, int out_size) {
    const float* x  = (const float*)d_in[0];
    const float* Wq = (const float*)d_in[1];
    const float* Wk = (const float*)d_in[2];
    const float* Wv = (const float*)d_in[3];
    const float* Wo = (const float*)d_in[4];
    float* out = (float*)d_out;

    __half *Qh, *Ql, *Kh, *Vh, *xh, *Ah, *W;
    cudaGetSymbolAddress((void**)&Qh, g_Qh);
    cudaGetSymbolAddress((void**)&Ql, g_Ql);
    cudaGetSymbolAddress((void**)&Kh, g_Kh);
    cudaGetSymbolAddress((void**)&Vh, g_Vh);
    cudaGetSymbolAddress((void**)&xh, g_xh);
    cudaGetSymbolAddress((void**)&Ah, g_Ah);
    cudaGetSymbolAddress((void**)&W,  g_W);

    static bool attr_done = false;
    if (!attr_done) {
        cudaFuncSetAttribute(gemm_qkv, cudaFuncAttributeMaxDynamicSharedMemorySize, GEMM_SMEM);
        cudaFuncSetAttribute(gemm_out, cudaFuncAttributeMaxDynamicSharedMemorySize, GEMM_SMEM);
        cudaFuncSetAttribute(attn_tc, cudaFuncAttributeMaxDynamicSharedMemorySize, ATTN_SMEM);
        attr_done = true;
    }

    const int CVT_N = NROWS * DD / 4 + DD * DD;   // 1M + 1M float4
    cvt_all<<<(CVT_N + 255) / 256, 256>>>(x, Wq, Wk, Wv, Wo, xh, W);

    gemm_qkv<<<dim3(24, 32), 512, GEMM_SMEM>>>(xh, W, Qh, Ql, Kh, Vh);

    attn_tc<<<dim3(TT / 64, HH, BB), 128, ATTN_SMEM>>>(Qh, Ql, Kh, Vh, Ah);

    gemm_out<<<dim3(8, 32), 512, GEMM_SMEM>>>(Ah, W + 3 * (size_t)DD * DD, out);
}

// round 9
// speedup vs baseline: 8.9307x; 1.0636x over previous
#include <cuda_runtime.h>
#include <cuda_fp16.h>
#include <cstdint>

#define BB 2
#define TT 2048
#define DD 1024
#define HH 16
#define DHH 64
#define NROWS (BB*TT)   // 4096

// Scratch (allocation-free rule: __device__ globals)
__device__ __half g_Qh[NROWS*DD];
__device__ __half g_Ql[NROWS*DD];
__device__ __half g_Kh[NROWS*DD];
__device__ __half g_Vh[NROWS*DD];
__device__ __half g_xh[NROWS*DD];
__device__ __half g_Ah[NROWS*DD];
__device__ __half g_W[4*DD*DD];

// ---------------------------------------------------------------------------
// helpers (portable PTX: cp.async / ldmatrix / mma.sync)
// ---------------------------------------------------------------------------
__device__ __forceinline__ uint32_t smem_u32(const void* p) {
    uint32_t a;
    asm("{ .reg .u64 t; cvta.to.shared.u64 t, %1; cvt.u32.u64 %0, t; }" : "=r"(a) : "l"(p));
    return a;
}
__device__ __forceinline__ void cp16(uint32_t dst, const void* src) {
    asm volatile("cp.async.cg.shared.global [%0], [%1], 16;" :: "r"(dst), "l"(src));
}
#define CP_COMMIT() asm volatile("cp.async.commit_group;" ::: "memory")
#define CP_WAIT(n)  asm volatile("cp.async.wait_group %0;" :: "n"(n) : "memory")

__device__ __forceinline__ void ldm_x4(uint32_t* r, uint32_t addr) {
    asm volatile("ldmatrix.sync.aligned.m8n8.x4.shared.b16 {%0,%1,%2,%3}, [%4];"
                 : "=r"(r[0]), "=r"(r[1]), "=r"(r[2]), "=r"(r[3]) : "r"(addr));
}
__device__ __forceinline__ void ldm_x4_t(uint32_t* r, uint32_t addr) {
    asm volatile("ldmatrix.sync.aligned.m8n8.x4.trans.shared.b16 {%0,%1,%2,%3}, [%4];"
                 : "=r"(r[0]), "=r"(r[1]), "=r"(r[2]), "=r"(r[3]) : "r"(addr));
}
__device__ __forceinline__ void mma_f16(float* d, const uint32_t* a, uint32_t b0, uint32_t b1) {
    asm volatile(
        "mma.sync.aligned.m16n8k16.row.col.f32.f16.f16.f32 "
        "{%0,%1,%2,%3}, {%4,%5,%6,%7}, {%8,%9}, {%0,%1,%2,%3};"
        : "+f"(d[0]), "+f"(d[1]), "+f"(d[2]), "+f"(d[3])
        : "r"(a[0]), "r"(a[1]), "r"(a[2]), "r"(a[3]), "r"(b0), "r"(b1));
}
__device__ __forceinline__ uint32_t pack_f16(float lo, float hi) {
    __half2 t = __halves2half2(__float2half(lo), __float2half(hi));
    return *(uint32_t*)&t;
}

// ---------------------------------------------------------------------------
// one-shot conversion: x and all 4 weights -> fp16
// ---------------------------------------------------------------------------
__global__ void __launch_bounds__(256) cvt_all(const float* __restrict__ x,
                                               const float* __restrict__ w0,
                                               const float* __restrict__ w1,
                                               const float* __restrict__ w2,
                                               const float* __restrict__ w3,
                                               __half* __restrict__ xh,
                                               __half* __restrict__ W) {
    const int XN4 = NROWS * DD / 4;        // 1M
    const int WN4 = DD * DD / 4;           // 256K
    int i = blockIdx.x * blockDim.x + threadIdx.x;
    if (i >= XN4 + 4 * WN4) return;
    const float* src;
    uint2* dst;
    int j;
    if (i < XN4) {
        src = x; dst = (uint2*)xh; j = i;
    } else {
        const int t = i - XN4;
        const int m = t / WN4;
        j = t - m * WN4;
        src = (m == 0) ? w0 : (m == 1) ? w1 : (m == 2) ? w2 : w3;
        dst = (uint2*)W + (size_t)m * WN4;
    }
    float4 v = ((const float4*)src)[j];
    __align__(8) __half h[4];
    h[0] = __float2half(v.x); h[1] = __float2half(v.y);
    h[2] = __float2half(v.z); h[3] = __float2half(v.w);
    dst[j] = *(const uint2*)h;
}

// ---------------------------------------------------------------------------
// GEMM mainloop: C[n,m] = sum_k A[n,k]*B[m,k], fp16 operands, fp32 acc.
// CTA tile 128x256, BK=32, 512 threads (16 warps = 4m x 4n, warp tile 32x64).
// 5 smem buffers (24KB each: A 8KB +0, B 16KB +8192), depth-4 pipeline,
// one __syncthreads per stage. Rows 64B, chunk swz c^=(r>>1)&3.
// ---------------------------------------------------------------------------
#define NSTAGE 5
#define STG 24576
#define GEMM_SMEM (NSTAGE * STG)   // 120 KB

__device__ __forceinline__ void gemm_mainloop(
    const __half* __restrict__ Ag, const __half* __restrict__ Bg,
    int n0, int m0, uint32_t sbase, float acc[2][8][4]) {
    const int tid  = threadIdx.x;
    const int wid  = tid >> 5;
    const int lane = tid & 31;
    const int warp_m = (wid & 3) * 32;
    const int warp_n = (wid >> 2) * 64;
    const int KT = DD / 32;   // 32

    // loader: 3 x 16B chunks per thread (A: 512 chunks, B: 1024 chunks)
    const int arow = tid >> 2;           // 0..127
    const int ac   = tid & 3;
    const uint32_t lda = (uint32_t)(arow * 64 + ((ac ^ ((arow >> 1) & 3)) * 16));
    const size_t ga = (size_t)(n0 + arow) * DD + ac * 8;
    const size_t gb1 = (size_t)(m0 + arow) * DD + ac * 8;          // B rows 0..127
    const size_t gb2 = (size_t)(m0 + 128 + arow) * DD + ac * 8;    // B rows 128..255
    const uint32_t ldb1 = (uint32_t)(arow * 64 + ((ac ^ ((arow >> 1) & 3)) * 16));
    const uint32_t ldb2 = (uint32_t)((128 + arow) * 64 + ((ac ^ (((128 + arow) >> 1) & 3)) * 16));

    auto load_stage = [&](int s) {
        const int k0 = s * 32;
        const uint32_t stg = sbase + (uint32_t)(s % NSTAGE) * STG;
        cp16(stg + 0    + lda,  Ag + ga  + k0);
        cp16(stg + 8192 + ldb1, Bg + gb1 + k0);
        cp16(stg + 8192 + ldb2, Bg + gb2 + k0);
        CP_COMMIT();
    };

    #pragma unroll
    for (int s = 0; s < 4; s++) load_stage(s);

    #pragma unroll
    for (int mt = 0; mt < 2; mt++)
        #pragma unroll
        for (int nt = 0; nt < 8; nt++)
            #pragma unroll
            for (int i = 0; i < 4; i++) acc[mt][nt][i] = 0.0f;

    const int a_r    = (lane & 15);
    const int a_csel = (lane >> 4);
    const int b_g    = (lane >> 3);
    const int b_r    = ((b_g >> 1) << 3) + (lane & 7);
    const int b_csel = (b_g & 1);

    for (int s = 0; s < KT; s++) {
        CP_WAIT(3);        // stage s resident
        __syncthreads();   // all warps past stage s-1 -> buf (s+4)%5 free
        if (s + 4 < KT) load_stage(s + 4);
        else            CP_COMMIT();

        const uint32_t stg = sbase + (uint32_t)(s % NSTAGE) * STG;
        #pragma unroll
        for (int kk = 0; kk < 32; kk += 16) {
            const int cbase = kk >> 3;
            uint32_t af[2][4], bf[4][4];
            #pragma unroll
            for (int mt = 0; mt < 2; mt++) {
                const int r = warp_m + mt * 16 + a_r;
                const int c = (cbase + a_csel) ^ ((r >> 1) & 3);
                ldm_x4(af[mt], stg + 0 + (uint32_t)(r * 64 + c * 16));
            }
            #pragma unroll
            for (int ng = 0; ng < 4; ng++) {
                const int r = warp_n + ng * 16 + b_r;
                const int c = (cbase + b_csel) ^ ((r >> 1) & 3);
                ldm_x4(bf[ng], stg + 8192 + (uint32_t)(r * 64 + c * 16));
            }
            #pragma unroll
            for (int mt = 0; mt < 2; mt++)
                #pragma unroll
                for (int nt = 0; nt < 8; nt++) {
                    const uint32_t b0 = bf[nt >> 1][(nt & 1) * 2];
                    const uint32_t b1 = bf[nt >> 1][(nt & 1) * 2 + 1];
                    mma_f16(acc[mt][nt], af[mt], b0, b1);
                }
        }
    }
}

// fused Q/K/V projection: grid (12, 32); blockIdx.x>>2 selects Wq/Wk/Wv.
__global__ void __launch_bounds__(512, 1) gemm_qkv(
    const __half* __restrict__ xh, const __half* __restrict__ W,
    __half* __restrict__ Qh, __half* __restrict__ Ql,
    __half* __restrict__ Kh, __half* __restrict__ Vh) {
    extern __shared__ __align__(128) char smem[];
    const int wsel = blockIdx.x >> 2;
    const int m0 = (blockIdx.x & 3) * 256;
    const int n0 = blockIdx.y * 128;

    float acc[2][8][4];
    gemm_mainloop(xh, W + (size_t)wsel * DD * DD, n0, m0, smem_u32(smem), acc);

    const int wid  = threadIdx.x >> 5;
    const int lane = threadIdx.x & 31;
    const int warp_m = (wid & 3) * 32;
    const int warp_n = (wid >> 2) * 64;

    #pragma unroll
    for (int mt = 0; mt < 2; mt++)
        #pragma unroll
        for (int nt = 0; nt < 8; nt++) {
            const int r   = n0 + warp_m + mt * 16 + (lane >> 2);
            const int col = m0 + warp_n + nt * 8 + (lane & 3) * 2;
            #pragma unroll
            for (int h2 = 0; h2 < 2; h2++) {
                const float v0 = acc[mt][nt][2 * h2], v1 = acc[mt][nt][2 * h2 + 1];
                const size_t o = (size_t)(r + 8 * h2) * DD + col;
                if (wsel == 0) {
                    const float h0 = __half2float(__float2half(v0));
                    const float h1 = __half2float(__float2half(v1));
                    *(uint32_t*)(Qh + o) = pack_f16(h0, h1);
                    *(uint32_t*)(Ql + o) = pack_f16(v0 - h0, v1 - h1);
                } else if (wsel == 1) {
                    *(uint32_t*)(Kh + o) = pack_f16(v0, v1);
                } else {
                    *(uint32_t*)(Vh + o) = pack_f16(v0, v1);
                }
            }
        }
}

// output projection: grid (4, 32); fp32 out.
__global__ void __launch_bounds__(512, 1) gemm_out(
    const __half* __restrict__ Ah, const __half* __restrict__ W,
    float* __restrict__ out) {
    extern __shared__ __align__(128) char smem[];
    const int m0 = blockIdx.x * 256;
    const int n0 = blockIdx.y * 128;

    float acc[2][8][4];
    gemm_mainloop(Ah, W, n0, m0, smem_u32(smem), acc);

    const int wid  = threadIdx.x >> 5;
    const int lane = threadIdx.x & 31;
    const int warp_m = (wid & 3) * 32;
    const int warp_n = (wid >> 2) * 64;

    #pragma unroll
    for (int mt = 0; mt < 2; mt++)
        #pragma unroll
        for (int nt = 0; nt < 8; nt++) {
            const int r   = n0 + warp_m + mt * 16 + (lane >> 2);
            const int col = m0 + warp_n + nt * 8 + (lane & 3) * 2;
            float2 v0 = {acc[mt][nt][0], acc[mt][nt][1]};
            float2 v1 = {acc[mt][nt][2], acc[mt][nt][3]};
            *(float2*)(out + (size_t)r * DD + col)       = v0;
            *(float2*)(out + (size_t)(r + 8) * DD + col) = v1;
        }
}

// ---------------------------------------------------------------------------
// Tensor-core sliding-window flash attention (fp16x2: Q & P split, K/V plain).
// CTA: 64 queries x (b,h); 4 warps, warp = 16 queries x 64 keys.
// ---------------------------------------------------------------------------
#define ATTN_SMEM (16384 + 2*16384)

__global__ void __launch_bounds__(128, 2) attn_tc(
    const __half* __restrict__ Qh, const __half* __restrict__ Ql,
    const __half* __restrict__ Kh, const __half* __restrict__ Vh,
    __half* __restrict__ Ah) {
    extern __shared__ __align__(128) char smem[];
    const uint32_t sb = smem_u32(smem);
    const int tid = threadIdx.x;
    const int lane = tid & 31;
    const int w = tid >> 5;
    const int q0 = blockIdx.x * 64;
    const int h = blockIdx.y;
    const int b = blockIdx.z;
    const size_t rowbase = (size_t)b * TT;
    const int col0 = h * DHH;

    const uint32_t QH_ = sb, QL_ = sb + 8192;
    auto KV_ = [&](int buf) { return sb + 16384 + (uint32_t)buf * 16384; };

    auto toff = [](int r, int cd) { return (uint32_t)(r * 128 + ((cd ^ (r & 7)) << 4)); };

    const int lr = tid >> 1;
    const int lc0 = (tid & 1) * 4;
    auto load_q = [&]() {
        const size_t g = (rowbase + q0 + lr) * DD + col0;
        #pragma unroll
        for (int c = 0; c < 4; c++) {
            const int cd = lc0 + c;
            cp16(QH_ + toff(lr, cd), Qh + g + cd * 8);
            cp16(QL_ + toff(lr, cd), Ql + g + cd * 8);
        }
    };
    auto load_kv = [&](int c, int buf) {
        const size_t g = (rowbase + c * 64 + lr) * DD + col0;
        const uint32_t base = KV_(buf);
        #pragma unroll
        for (int cc = 0; cc < 4; cc++) {
            const int cd = lc0 + cc;
            const uint32_t d = toff(lr, cd);
            cp16(base + 0    + d, Kh + g + cd * 8);
            cp16(base + 8192 + d, Vh + g + cd * 8);
        }
    };

    const int c_lo = (q0 >= 128) ? ((q0 - 128) >> 6) : 0;
    const int c_hi = q0 >> 6;

    load_q();
    load_kv(c_lo, c_lo & 1);
    CP_COMMIT();

    float m[2] = {-1e30f, -1e30f}, l[2] = {0.0f, 0.0f};
    float accO[8][4];
    #pragma unroll
    for (int nt = 0; nt < 8; nt++)
        #pragma unroll
        for (int i = 0; i < 4; i++) accO[nt][i] = 0.0f;

    uint32_t qhf[4][4], qlf[4][4];
    bool qloaded = false;

    const int row_in_warp = lane >> 2;
    const int colpair = (lane & 3) * 2;

    for (int c = c_lo; c <= c_hi; c++) {
        const int buf = c & 1;
        if (c < c_hi) { load_kv(c + 1, (c + 1) & 1); CP_COMMIT(); CP_WAIT(1); }
        else          { CP_WAIT(0); }
        __syncthreads();

        if (!qloaded) {
            qloaded = true;
            #pragma unroll
            for (int ks = 0; ks < 4; ks++) {
                const int r = w * 16 + (lane & 15);
                const int cd = 2 * ks + (lane >> 4);
                ldm_x4(qhf[ks], QH_ + toff(r, cd));
                ldm_x4(qlf[ks], QL_ + toff(r, cd));
            }
        }

        // ---- S = Q K^T (fp16x2) ----
        float sacc[8][4];
        #pragma unroll
        for (int nt = 0; nt < 8; nt++)
            #pragma unroll
            for (int i = 0; i < 4; i++) sacc[nt][i] = 0.0f;

        const uint32_t kh_base = KV_(buf);
        const int krow = (lane & 7) + ((lane & 16) >> 1);
        const int kcd0 = (lane >> 3) & 1;
        #pragma unroll
        for (int ks = 0; ks < 4; ks++) {
            #pragma unroll
            for (int ng = 0; ng < 4; ng++) {
                const int rn = ng * 16 + krow;
                const int cd = 2 * ks + kcd0;
                uint32_t bh[4];
                ldm_x4(bh, kh_base + toff(rn, cd));
                mma_f16(sacc[2*ng],   qhf[ks], bh[0], bh[1]);
                mma_f16(sacc[2*ng],   qlf[ks], bh[0], bh[1]);
                mma_f16(sacc[2*ng+1], qhf[ks], bh[2], bh[3]);
                mma_f16(sacc[2*ng+1], qlf[ks], bh[2], bh[3]);
            }
        }

        // ---- mask + scale + online softmax ----
        const int kbase = c * 64;
        float rmax[2] = {-1e30f, -1e30f};
        #pragma unroll
        for (int nt = 0; nt < 8; nt++)
            #pragma unroll
            for (int e2 = 0; e2 < 4; e2++) {
                const int h2 = e2 >> 1;
                const int key = kbase + nt * 8 + colpair + (e2 & 1);
                const int iq  = q0 + w * 16 + row_in_warp + 8 * h2;
                float s = sacc[nt][e2] * 0.125f;
                s = (key <= iq && key + 128 >= iq) ? s : -1e30f;
                sacc[nt][e2] = s;
                rmax[h2] = fmaxf(rmax[h2], s);
            }
        #pragma unroll
        for (int h2 = 0; h2 < 2; h2++) {
            rmax[h2] = fmaxf(rmax[h2], __shfl_xor_sync(0xffffffffu, rmax[h2], 1));
            rmax[h2] = fmaxf(rmax[h2], __shfl_xor_sync(0xffffffffu, rmax[h2], 2));
        }
        float corr[2], rsum[2] = {0.0f, 0.0f};
        #pragma unroll
        for (int h2 = 0; h2 < 2; h2++) {
            const float newm = fmaxf(m[h2], rmax[h2]);
            corr[h2] = __expf(m[h2] - newm);
            m[h2] = newm;
        }
        #pragma unroll
        for (int nt = 0; nt < 8; nt++)
            #pragma unroll
            for (int e2 = 0; e2 < 4; e2++) {
                const int h2 = e2 >> 1;
                const float p = __expf(sacc[nt][e2] - m[h2]);
                sacc[nt][e2] = p;
                rsum[h2] += p;
            }
        #pragma unroll
        for (int h2 = 0; h2 < 2; h2++) {
            rsum[h2] += __shfl_xor_sync(0xffffffffu, rsum[h2], 1);
            rsum[h2] += __shfl_xor_sync(0xffffffffu, rsum[h2], 2);
            l[h2] = l[h2] * corr[h2] + rsum[h2];
        }
        #pragma unroll
        for (int nt = 0; nt < 8; nt++) {
            accO[nt][0] *= corr[0]; accO[nt][1] *= corr[0];
            accO[nt][2] *= corr[1]; accO[nt][3] *= corr[1];
        }

        // ---- P fragments (registers, hi/lo split) ----
        uint32_t ph[4][4], pl[4][4];
        #pragma unroll
        for (int js = 0; js < 4; js++) {
            #pragma unroll
            for (int half16 = 0; half16 < 2; half16++) {
                const int nt = 2 * js + half16;
                #pragma unroll
                for (int h2 = 0; h2 < 2; h2++) {
                    const float p0 = sacc[nt][2 * h2], p1 = sacc[nt][2 * h2 + 1];
                    const float h0 = __half2float(__float2half(p0));
                    const float h1 = __half2float(__float2half(p1));
                    ph[js][half16 * 2 + h2] = pack_f16(h0, h1);
                    pl[js][half16 * 2 + h2] = pack_f16(p0 - h0, p1 - h1);
                }
            }
        }

        // ---- O += P V (fp16x2, V via ldmatrix.trans) ----
        const uint32_t vh_base = KV_(buf) + 8192;
        const int vrow = (lane & 7) + (lane & 8);
        const int vcd0 = lane >> 4;
        #pragma unroll
        for (int js = 0; js < 4; js++) {
            #pragma unroll
            for (int ng = 0; ng < 4; ng++) {
                const int rv = js * 16 + vrow;
                const int cd = 2 * ng + vcd0;
                uint32_t vhf[4];
                ldm_x4_t(vhf, vh_base + toff(rv, cd));
                mma_f16(accO[2*ng],   ph[js], vhf[0], vhf[1]);
                mma_f16(accO[2*ng],   pl[js], vhf[0], vhf[1]);
                mma_f16(accO[2*ng+1], ph[js], vhf[2], vhf[3]);
                mma_f16(accO[2*ng+1], pl[js], vhf[2], vhf[3]);
            }
        }
        __syncthreads();
    }

    // ---- write O (single fp16) ----
    const float inv0 = 1.0f / l[0], inv1 = 1.0f / l[1];
    #pragma unroll
    for (int nt = 0; nt < 8; nt++) {
        #pragma unroll
        for (int h2 = 0; h2 < 2; h2++) {
            const float inv = h2 ? inv1 : inv0;
            const int gi = q0 + w * 16 + row_in_warp + 8 * h2;
            const size_t o = (rowbase + gi) * DD + col0 + nt * 8 + colpair;
            *(uint32_t*)(Ah + o) = pack_f16(accO[nt][2 * h2] * inv,
                                            accO[nt][2 * h2 + 1] * inv);
        }
    }
}

// ---------------------------------------------------------------------------
extern "C" void kernel_launch(void* const* d_in, const int* in_sizes, int n_in,
                              void* d_out, int out_size) {
    const float* x  = (const float*)d_in[0];
    const float* Wq = (const float*)d_in[1];
    const float* Wk = (const float*)d_in[2];
    const float* Wv = (const float*)d_in[3];
    const float* Wo = (const float*)d_in[4];
    float* out = (float*)d_out;

    __half *Qh, *Ql, *Kh, *Vh, *xh, *Ah, *W;
    cudaGetSymbolAddress((void**)&Qh, g_Qh);
    cudaGetSymbolAddress((void**)&Ql, g_Ql);
    cudaGetSymbolAddress((void**)&Kh, g_Kh);
    cudaGetSymbolAddress((void**)&Vh, g_Vh);
    cudaGetSymbolAddress((void**)&xh, g_xh);
    cudaGetSymbolAddress((void**)&Ah, g_Ah);
    cudaGetSymbolAddress((void**)&W,  g_W);

    static bool attr_done = false;
    if (!attr_done) {
        cudaFuncSetAttribute(gemm_qkv, cudaFuncAttributeMaxDynamicSharedMemorySize, GEMM_SMEM);
        cudaFuncSetAttribute(gemm_out, cudaFuncAttributeMaxDynamicSharedMemorySize, GEMM_SMEM);
        cudaFuncSetAttribute(attn_tc, cudaFuncAttributeMaxDynamicSharedMemorySize, ATTN_SMEM);
        attr_done = true;
    }

    const int CVT_N = NROWS * DD / 4 + DD * DD;   // 2M float4
    cvt_all<<<(CVT_N + 255) / 256, 256>>>(x, Wq, Wk, Wv, Wo, xh, W);

    gemm_qkv<<<dim3(12, 32), 512, GEMM_SMEM>>>(xh, W, Qh, Ql, Kh, Vh);

    attn_tc<<<dim3(TT / 64, HH, BB), 128, ATTN_SMEM>>>(Qh, Ql, Kh, Vh, Ah);

    gemm_out<<<dim3(4, 32), 512, GEMM_SMEM>>>(Ah, W + 3 * (size_t)DD * DD, out);
}